// round 7
// baseline (speedup 1.0000x reference)
#include <cuda_runtime.h>
#include <cstdint>
#include <cstddef>

#define H_    300000
#define CIN   16
#define COUT  32
#define KK    27
#define HB    128                     // h per block
#define TB    128                     // threads per block
#define NBLK  ((H_ + HB - 1) / HB)    // 2344
#define NIDX  (H_ * KK)               // 8,100,000
#define COLP  132                     // col row pitch (floats)
#define COLSZ 2120                    // floats per col buffer (max addr 2116, pad)
#define WSZ   (KK * CIN * COUT)       // 13824 weight floats

// Scratch (static device globals: allocation-free per harness rules)
__device__ float4 g_xT4[(size_t)H_ * 4];     // 19.2 MB: x transposed to [h][i]
__device__ float  g_wpk[WSZ];                // 55 KB: weights repacked [(k*16+i)*32+o]
__device__ float  g_partials[64 * NBLK];     // rows 0..31 sum(y), 32..63 sum(y^2)
__device__ float  g_scale[COUT];
__device__ float  g_bias[COUT];
__device__ int    g_is64;

// packed f32x2 helpers (sm_103a FFMA2 — only reachable via PTX)
__device__ __forceinline__ unsigned long long fma_f32x2(unsigned long long a,
                                                        unsigned long long b,
                                                        unsigned long long c) {
    unsigned long long d;
    asm("fma.rn.f32x2 %0, %1, %2, %3;" : "=l"(d) : "l"(a), "l"(b), "l"(c));
    return d;
}
__device__ __forceinline__ unsigned long long pack_dup(float v) {
    unsigned long long d;
    unsigned int u = __float_as_uint(v);
    asm("mov.b64 %0, {%1, %2};" : "=l"(d) : "r"(u), "r"(u));
    return d;
}
__device__ __forceinline__ void unpack2(unsigned long long p, float& lo, float& hi) {
    unsigned int a, b;
    asm("mov.b64 {%0, %1}, %2;" : "=r"(a), "=r"(b) : "l"(p));
    lo = __uint_as_float(a);
    hi = __uint_as_float(b);
}
__device__ __forceinline__ unsigned long long pack2(float lo, float hi) {
    unsigned long long d;
    asm("mov.b64 %0, {%1, %2};" : "=l"(d) : "r"(__float_as_uint(lo)), "r"(__float_as_uint(hi)));
    return d;
}

// col addressing: row i at i*COLP + ((i>>3)&1)*8  (keeps STS conflict-free
// across the 4 quads while preserving 16B alignment for LDS.128)
__device__ __forceinline__ int col_row_off(int i) {
    return i * COLP + ((i >> 3) & 1) * 8;
}

// ---------------------------------------------------------------------------
// Kernel 0: detect int64 vs int32 neigh (JAX x64 off => i32). Sample odd words.
// ---------------------------------------------------------------------------
__global__ void detect_kernel(const unsigned int* __restrict__ nv) {
    __shared__ int ok;
    if (threadIdx.x == 0) ok = 1;
    __syncthreads();
    unsigned int v = nv[threadIdx.x * 2000 + 1];   // max idx < 2.05M < 8.1M words
    if (v != 0u && v != 0xFFFFFFFFu) ok = 0;       // benign race: only writes 0
    __syncthreads();
    if (threadIdx.x == 0) g_is64 = ok;
}

// ---------------------------------------------------------------------------
// Kernel 1: repack weights w[o][i][k] -> g_wpk[(k*16+i)*32+o] (o-contiguous).
// ---------------------------------------------------------------------------
__global__ void repack_w_kernel(const float* __restrict__ w) {
    int t = blockIdx.x * blockDim.x + threadIdx.x;
    if (t < WSZ) {
        int o = t / (CIN * KK);
        int r = t % (CIN * KK);
        int i = r / KK;
        int k = r % KK;
        g_wpk[(k * CIN + i) * COUT + o] = w[t];
    }
}

// ---------------------------------------------------------------------------
// Kernel 2: transpose x[i][h] -> xT[h][i]; each gather row becomes one 64B line.
// ---------------------------------------------------------------------------
__global__ void transpose_x_kernel(const float* __restrict__ x) {
    int h = blockIdx.x * blockDim.x + threadIdx.x;
    if (h < H_) {
        float v[CIN];
#pragma unroll
        for (int i = 0; i < CIN; i++) v[i] = x[(size_t)i * H_ + h];
#pragma unroll
        for (int j = 0; j < 4; j++)
            g_xT4[(size_t)h * 4 + j] =
                make_float4(v[4 * j], v[4 * j + 1], v[4 * j + 2], v[4 * j + 3]);
    }
}

// ---------------------------------------------------------------------------
// Kernel 3: register-blocked GEMM y[32,128] = W[32,432] * col[432,128] per
// block. Double-buffered cooperative gather; FFMA2; weights via uniform
// broadcast __ldg (L1-resident, 1 wf per load); indices staged once per block;
// conflict-free STS swizzle. 4 warps: warp = o-group. Thread tile 8o x 4h.
// ---------------------------------------------------------------------------
__global__ void __launch_bounds__(TB, 6) conv_kernel(const int* __restrict__ neigh32,
                                                     float* __restrict__ out) {
    __shared__ float col[2 * COLSZ];   // 16960 B
    __shared__ int   sidx[HB * KK];    // 13824 B

    const int tid  = threadIdx.x;
    const int lane = tid & 31;
    const int wid  = tid >> 5;        // 0..3 = o-group
    const int h0   = blockIdx.x * HB;
    const int og   = wid * 8;         // warp's 8 output channels
    const int hg   = lane * 4;        // thread's 4 h (contiguous)

    // Stage this block's 128*27 indices once (coalesced; i64 low-word read).
    {
        const int is64 = g_is64;
        const int base = h0 * KK;
#pragma unroll 1
        for (int t = tid; t < HB * KK; t += TB) {
            int gi = base + t;
            int v = -1;
            if (gi < NIDX) v = neigh32[is64 ? 2 * gi : gi];
            sidx[t] = v;
        }
    }
    __syncthreads();

    const int q     = tid & 3;        // which float4 of a gathered row
    const int rbase = tid >> 2;       // 0..31; rows r = rbase + 32j
    const int sbase = 4 * q * COLP + (q >> 1) * 8;   // swizzled store base

    // Cooperative gather of col tile for step k: 4 lanes fetch one 64B row.
    auto gather = [&](int k, float* dst) {
#pragma unroll
        for (int j = 0; j < 4; j++) {
            int r   = rbase + 32 * j;
            int idx = sidx[r * KK + k];
            float4 v = make_float4(0.f, 0.f, 0.f, 0.f);
            if (idx >= 0 && idx < H_) v = g_xT4[(size_t)idx * 4 + q];
            float* p = dst + sbase + r;
            p[0 * COLP] = v.x;
            p[1 * COLP] = v.y;
            p[2 * COLP] = v.z;
            p[3 * COLP] = v.w;
        }
    };

    gather(0, col);
    __syncthreads();

    unsigned long long acc[4][4];   // [o-pair][h]
#pragma unroll
    for (int a = 0; a < 4; a++)
#pragma unroll
        for (int b = 0; b < 4; b++) acc[a][b] = 0ull;

#pragma unroll 1
    for (int k = 0; k < KK; k++) {
        const float* cc = col + (k & 1) * COLSZ;
        float*       cn = col + ((k + 1) & 1) * COLSZ;
        if (k + 1 < KK) gather(k + 1, cn);

#pragma unroll
        for (int i = 0; i < CIN; i++) {
            float4 c4 = *reinterpret_cast<const float4*>(cc + col_row_off(i) + hg);
            unsigned long long cd[4] = {pack_dup(c4.x), pack_dup(c4.y),
                                        pack_dup(c4.z), pack_dup(c4.w)};
            // 8 weights for this warp: two uniform broadcast LDG.128 (L1-hit)
            const float4* wp4 =
                reinterpret_cast<const float4*>(g_wpk + (k * CIN + i) * COUT + og);
            float4 wa = __ldg(wp4);
            float4 wb = __ldg(wp4 + 1);
            unsigned long long w01 = pack2(wa.x, wa.y), w23 = pack2(wa.z, wa.w);
            unsigned long long w45 = pack2(wb.x, wb.y), w67 = pack2(wb.z, wb.w);
#pragma unroll
            for (int hh = 0; hh < 4; hh++) {
                acc[0][hh] = fma_f32x2(w01, cd[hh], acc[0][hh]);
                acc[1][hh] = fma_f32x2(w23, cd[hh], acc[1][hh]);
                acc[2][hh] = fma_f32x2(w45, cd[hh], acc[2][hh]);
                acc[3][hh] = fma_f32x2(w67, cd[hh], acc[3][hh]);
            }
        }
        __syncthreads();
    }

    // Unpack, write y (coalesced float4 per o), per-warp BN partials.
    const bool valid = (h0 + hg) < H_;   // quad-granular: H_ % 4 == 0
    float s[8], ss[8];
#pragma unroll
    for (int op = 0; op < 4; op++) {
        float lo[4], hi[4];
#pragma unroll
        for (int hh = 0; hh < 4; hh++) unpack2(acc[op][hh], lo[hh], hi[hh]);
        if (valid) {
            *reinterpret_cast<float4*>(out + (size_t)(og + 2 * op) * H_ + h0 + hg) =
                make_float4(lo[0], lo[1], lo[2], lo[3]);
            *reinterpret_cast<float4*>(out + (size_t)(og + 2 * op + 1) * H_ + h0 + hg) =
                make_float4(hi[0], hi[1], hi[2], hi[3]);
        }
        s[2 * op]      = lo[0] + lo[1] + lo[2] + lo[3];
        s[2 * op + 1]  = hi[0] + hi[1] + hi[2] + hi[3];
        ss[2 * op]     = lo[0] * lo[0] + lo[1] * lo[1] + lo[2] * lo[2] + lo[3] * lo[3];
        ss[2 * op + 1] = hi[0] * hi[0] + hi[1] * hi[1] + hi[2] * hi[2] + hi[3] * hi[3];
    }
#pragma unroll
    for (int oo = 0; oo < 8; oo++) {
        float v = s[oo], qv = ss[oo];
#pragma unroll
        for (int sft = 16; sft > 0; sft >>= 1) {
            v  += __shfl_down_sync(0xffffffffu, v, sft);
            qv += __shfl_down_sync(0xffffffffu, qv, sft);
        }
        if (lane == 0) {
            g_partials[(og + oo) * NBLK + blockIdx.x]      = v;
            g_partials[(32 + og + oo) * NBLK + blockIdx.x] = qv;
        }
    }
}

// ---------------------------------------------------------------------------
// Kernel 4: one block per channel; deterministic fp64 reduction -> scale/bias.
// ---------------------------------------------------------------------------
__global__ void stats_kernel(const float* __restrict__ gamma,
                             const float* __restrict__ beta) {
    const int o = blockIdx.x;
    double s1 = 0.0, s2 = 0.0;
    for (int b = threadIdx.x; b < NBLK; b += blockDim.x) {
        s1 += (double)g_partials[o * NBLK + b];
        s2 += (double)g_partials[(32 + o) * NBLK + b];
    }
    __shared__ double r1[256], r2[256];
    r1[threadIdx.x] = s1;
    r2[threadIdx.x] = s2;
    __syncthreads();
    for (int sft = 128; sft > 0; sft >>= 1) {
        if (threadIdx.x < sft) {
            r1[threadIdx.x] += r1[threadIdx.x + sft];
            r2[threadIdx.x] += r2[threadIdx.x + sft];
        }
        __syncthreads();
    }
    if (threadIdx.x == 0) {
        double mean = r1[0] / (double)H_;
        double var  = r2[0] / (double)H_ - mean * mean;
        float rstd  = rsqrtf((float)(var + 1e-5));
        float sc    = rstd * gamma[o];
        g_scale[o]  = sc;
        g_bias[o]   = beta[o] - (float)mean * sc;
    }
}

// ---------------------------------------------------------------------------
// Kernel 5: normalize in place (float4; H % 4 == 0).
// ---------------------------------------------------------------------------
__global__ void bn_kernel(float* __restrict__ out) {
    const int o = blockIdx.y;
    const int t = blockIdx.x * blockDim.x + threadIdx.x;
    const float sc = g_scale[o], bi = g_bias[o];
    float4* p = reinterpret_cast<float4*>(out + (size_t)o * H_);
    if (t < H_ / 4) {
        float4 v = p[t];
        v.x = v.x * sc + bi;
        v.y = v.y * sc + bi;
        v.z = v.z * sc + bi;
        v.w = v.w * sc + bi;
        p[t] = v;
    }
}

// ---------------------------------------------------------------------------
extern "C" void kernel_launch(void* const* d_in, const int* in_sizes, int n_in,
                              void* d_out, int out_size) {
    const float* x     = (const float*)d_in[0];  // (1,16,300000,1)
    const float* w     = (const float*)d_in[1];  // (32,16,27)
    const float* gamma = (const float*)d_in[2];  // (32,)
    const float* beta  = (const float*)d_in[3];  // (32,)
    const void*  neigh = d_in[4];                // (300000,27) i64 or i32
    float*       out   = (float*)d_out;          // (1,32,300000,1)

    detect_kernel<<<1, 1024>>>((const unsigned int*)neigh);
    repack_w_kernel<<<(WSZ + 255) / 256, 256>>>(w);
    transpose_x_kernel<<<(H_ + 255) / 256, 256>>>(x);
    conv_kernel<<<NBLK, TB>>>((const int*)neigh, out);
    stats_kernel<<<COUT, 256>>>(gamma, beta);
    bn_kernel<<<dim3((H_ / 4 + 255) / 256, COUT), 256>>>(out);
}

// round 8
// speedup vs baseline: 1.0710x; 1.0710x over previous
#include <cuda_runtime.h>
#include <cstdint>
#include <cstddef>

#define H_    300000
#define CIN   16
#define COUT  32
#define KK    27
#define HB    128                     // h per block
#define TB    128                     // threads per block
#define NBLK  ((H_ + HB - 1) / HB)    // 2344
#define NIDX  (H_ * KK)               // 8,100,000
#define PITCH 132                     // col row pitch (floats, 16B-aligned)
#define COLSZ (CIN * PITCH)           // 2112 floats per col buffer
#define WSZ   (KK * CIN * COUT)       // 13824 weight floats

// Scratch (static device globals: allocation-free per harness rules)
__device__ float4 g_xT4[(size_t)H_ * 4];     // 19.2 MB: x transposed to [h][i]
__device__ float  g_wpk[WSZ];                // 55 KB: weights repacked [(k*16+i)*32+o]
__device__ float  g_partials[64 * NBLK];     // rows 0..31 sum(y), 32..63 sum(y^2)
__device__ float  g_scale[COUT];
__device__ float  g_bias[COUT];
__device__ int    g_is64;

// packed f32x2 helpers (sm_103a FFMA2 — only reachable via PTX)
__device__ __forceinline__ unsigned long long fma_f32x2(unsigned long long a,
                                                        unsigned long long b,
                                                        unsigned long long c) {
    unsigned long long d;
    asm("fma.rn.f32x2 %0, %1, %2, %3;" : "=l"(d) : "l"(a), "l"(b), "l"(c));
    return d;
}
__device__ __forceinline__ unsigned long long pack_dup(float v) {
    unsigned long long d;
    unsigned int u = __float_as_uint(v);
    asm("mov.b64 %0, {%1, %2};" : "=l"(d) : "r"(u), "r"(u));
    return d;
}
__device__ __forceinline__ void unpack2(unsigned long long p, float& lo, float& hi) {
    unsigned int a, b;
    asm("mov.b64 {%0, %1}, %2;" : "=r"(a), "=r"(b) : "l"(p));
    lo = __uint_as_float(a);
    hi = __uint_as_float(b);
}
__device__ __forceinline__ unsigned long long pack2(float lo, float hi) {
    unsigned long long d;
    asm("mov.b64 %0, {%1, %2};" : "=l"(d) : "r"(__float_as_uint(lo)), "r"(__float_as_uint(hi)));
    return d;
}

// ---------------------------------------------------------------------------
// Kernel 0: detect int64 vs int32 neigh (JAX x64 off => i32). Sample odd words.
// ---------------------------------------------------------------------------
__global__ void detect_kernel(const unsigned int* __restrict__ nv) {
    __shared__ int ok;
    if (threadIdx.x == 0) ok = 1;
    __syncthreads();
    unsigned int v = nv[threadIdx.x * 2000 + 1];   // max idx < 2.05M < 8.1M words
    if (v != 0u && v != 0xFFFFFFFFu) ok = 0;       // benign race: only writes 0
    __syncthreads();
    if (threadIdx.x == 0) g_is64 = ok;
}

// ---------------------------------------------------------------------------
// Kernel 1: repack weights w[o][i][k] -> g_wpk[(k*16+i)*32+o] (o-contiguous).
// ---------------------------------------------------------------------------
__global__ void repack_w_kernel(const float* __restrict__ w) {
    int t = blockIdx.x * blockDim.x + threadIdx.x;
    if (t < WSZ) {
        int o = t / (CIN * KK);
        int r = t % (CIN * KK);
        int i = r / KK;
        int k = r % KK;
        g_wpk[(k * CIN + i) * COUT + o] = w[t];
    }
}

// ---------------------------------------------------------------------------
// Kernel 2: transpose x[i][h] -> xT[h][i]; each gather row becomes one 64B line.
// ---------------------------------------------------------------------------
__global__ void transpose_x_kernel(const float* __restrict__ x) {
    int h = blockIdx.x * blockDim.x + threadIdx.x;
    if (h < H_) {
        float v[CIN];
#pragma unroll
        for (int i = 0; i < CIN; i++) v[i] = x[(size_t)i * H_ + h];
#pragma unroll
        for (int j = 0; j < 4; j++)
            g_xT4[(size_t)h * 4 + j] =
                make_float4(v[4 * j], v[4 * j + 1], v[4 * j + 2], v[4 * j + 3]);
    }
}

// ---------------------------------------------------------------------------
// Kernel 3: register-blocked GEMM y[32,128] = W[32,432] * col[432,128] per
// block — R5 structure (inline idx LDG, no swizzle, __ldg weights) with
// 2 k-steps per barrier phase on 4 rotating col buffers:
// 13 syncs instead of 27, 8 gather LDGs in flight per phase.
// 4 warps: warp = o-group. Thread tile 8o x 4h, FFMA2 math.
// ---------------------------------------------------------------------------
__global__ void __launch_bounds__(TB, 6) conv_kernel(const int* __restrict__ neigh32,
                                                     float* __restrict__ out) {
    __shared__ float col[4 * COLSZ];   // 33792 B

    const int tid  = threadIdx.x;
    const int lane = tid & 31;
    const int wid  = tid >> 5;        // 0..3 = o-group
    const int h0   = blockIdx.x * HB;
    const int og   = wid * 8;         // warp's 8 output channels
    const int hg   = lane * 4;        // thread's 4 h (contiguous)

    const int is64  = g_is64;
    const int q     = tid & 3;        // which float4 of a gathered row
    const int rbase = tid >> 2;       // 0..31; rows r = rbase + 32j

    // Cooperative gather of col tile for step k: 4 lanes fetch one 64B row.
    auto gather = [&](int k, float* dst) {
#pragma unroll
        for (int j = 0; j < 4; j++) {
            int r = rbase + 32 * j;
            int h = h0 + r;
            int idx = -1;
            if (h < H_) {
                int gi = h * KK + k;                 // <= 8.1M, fits int
                idx = neigh32[is64 ? 2 * gi : gi];   // low word: sign-safe
            }
            float4 v = make_float4(0.f, 0.f, 0.f, 0.f);
            if (idx >= 0 && idx < H_) v = g_xT4[(size_t)idx * 4 + q];
            float* p = dst + (4 * q) * PITCH + r;
            p[0 * PITCH] = v.x;
            p[1 * PITCH] = v.y;
            p[2 * PITCH] = v.z;
            p[3 * PITCH] = v.w;
        }
    };

    unsigned long long acc[4][4];   // [o-pair][h]
#pragma unroll
    for (int a = 0; a < 4; a++)
#pragma unroll
        for (int b = 0; b < 4; b++) acc[a][b] = 0ull;

    // One k-step of the register-blocked FFMA2 GEMM from buffer cc.
    auto compute = [&](const float* cc, int k) {
#pragma unroll
        for (int i = 0; i < CIN; i++) {
            float4 c4 = *reinterpret_cast<const float4*>(cc + i * PITCH + hg);
            unsigned long long cd[4] = {pack_dup(c4.x), pack_dup(c4.y),
                                        pack_dup(c4.z), pack_dup(c4.w)};
            const float4* wp4 =
                reinterpret_cast<const float4*>(g_wpk + (k * CIN + i) * COUT + og);
            float4 wa = __ldg(wp4);
            float4 wb = __ldg(wp4 + 1);
            unsigned long long w01 = pack2(wa.x, wa.y), w23 = pack2(wa.z, wa.w);
            unsigned long long w45 = pack2(wb.x, wb.y), w67 = pack2(wb.z, wb.w);
#pragma unroll
            for (int hh = 0; hh < 4; hh++) {
                acc[0][hh] = fma_f32x2(w01, cd[hh], acc[0][hh]);
                acc[1][hh] = fma_f32x2(w23, cd[hh], acc[1][hh]);
                acc[2][hh] = fma_f32x2(w45, cd[hh], acc[2][hh]);
                acc[3][hh] = fma_f32x2(w67, cd[hh], acc[3][hh]);
            }
        }
    };

    gather(0, col);
    gather(1, col + COLSZ);
    __syncthreads();

#pragma unroll 1
    for (int p = 0; p < 13; p++) {
        const int k0 = 2 * p;
        const float* b0 = col + (k0 & 3) * COLSZ;
        const float* b1 = col + ((k0 + 1) & 3) * COLSZ;
        // prefetch next phase's two tiles into the other two buffers
        gather(k0 + 2, col + ((k0 + 2) & 3) * COLSZ);          // k0+2 <= 26 always
        if (k0 + 3 < KK) gather(k0 + 3, col + ((k0 + 3) & 3) * COLSZ);
        compute(b0, k0);
        compute(b1, k0 + 1);
        __syncthreads();
    }
    compute(col + ((KK - 1) & 3) * COLSZ, KK - 1);   // k = 26, buffer 2

    // Unpack, write y (coalesced float4 per o), per-warp BN partials.
    const bool valid = (h0 + hg) < H_;   // quad-granular: H_ % 4 == 0
    float s[8], ss[8];
#pragma unroll
    for (int op = 0; op < 4; op++) {
        float lo[4], hi[4];
#pragma unroll
        for (int hh = 0; hh < 4; hh++) unpack2(acc[op][hh], lo[hh], hi[hh]);
        if (valid) {
            *reinterpret_cast<float4*>(out + (size_t)(og + 2 * op) * H_ + h0 + hg) =
                make_float4(lo[0], lo[1], lo[2], lo[3]);
            *reinterpret_cast<float4*>(out + (size_t)(og + 2 * op + 1) * H_ + h0 + hg) =
                make_float4(hi[0], hi[1], hi[2], hi[3]);
        }
        s[2 * op]      = lo[0] + lo[1] + lo[2] + lo[3];
        s[2 * op + 1]  = hi[0] + hi[1] + hi[2] + hi[3];
        ss[2 * op]     = lo[0] * lo[0] + lo[1] * lo[1] + lo[2] * lo[2] + lo[3] * lo[3];
        ss[2 * op + 1] = hi[0] * hi[0] + hi[1] * hi[1] + hi[2] * hi[2] + hi[3] * hi[3];
    }
#pragma unroll
    for (int oo = 0; oo < 8; oo++) {
        float v = s[oo], qv = ss[oo];
#pragma unroll
        for (int sft = 16; sft > 0; sft >>= 1) {
            v  += __shfl_down_sync(0xffffffffu, v, sft);
            qv += __shfl_down_sync(0xffffffffu, qv, sft);
        }
        if (lane == 0) {
            g_partials[(og + oo) * NBLK + blockIdx.x]      = v;
            g_partials[(32 + og + oo) * NBLK + blockIdx.x] = qv;
        }
    }
}

// ---------------------------------------------------------------------------
// Kernel 4: one block per channel; deterministic fp64 reduction -> scale/bias.
// ---------------------------------------------------------------------------
__global__ void stats_kernel(const float* __restrict__ gamma,
                             const float* __restrict__ beta) {
    const int o = blockIdx.x;
    double s1 = 0.0, s2 = 0.0;
    for (int b = threadIdx.x; b < NBLK; b += blockDim.x) {
        s1 += (double)g_partials[o * NBLK + b];
        s2 += (double)g_partials[(32 + o) * NBLK + b];
    }
    __shared__ double r1[256], r2[256];
    r1[threadIdx.x] = s1;
    r2[threadIdx.x] = s2;
    __syncthreads();
    for (int sft = 128; sft > 0; sft >>= 1) {
        if (threadIdx.x < sft) {
            r1[threadIdx.x] += r1[threadIdx.x + sft];
            r2[threadIdx.x] += r2[threadIdx.x + sft];
        }
        __syncthreads();
    }
    if (threadIdx.x == 0) {
        double mean = r1[0] / (double)H_;
        double var  = r2[0] / (double)H_ - mean * mean;
        float rstd  = rsqrtf((float)(var + 1e-5));
        float sc    = rstd * gamma[o];
        g_scale[o]  = sc;
        g_bias[o]   = beta[o] - (float)mean * sc;
    }
}

// ---------------------------------------------------------------------------
// Kernel 5: normalize in place (float4; H % 4 == 0).
// ---------------------------------------------------------------------------
__global__ void bn_kernel(float* __restrict__ out) {
    const int o = blockIdx.y;
    const int t = blockIdx.x * blockDim.x + threadIdx.x;
    const float sc = g_scale[o], bi = g_bias[o];
    float4* p = reinterpret_cast<float4*>(out + (size_t)o * H_);
    if (t < H_ / 4) {
        float4 v = p[t];
        v.x = v.x * sc + bi;
        v.y = v.y * sc + bi;
        v.z = v.z * sc + bi;
        v.w = v.w * sc + bi;
        p[t] = v;
    }
}

// ---------------------------------------------------------------------------
extern "C" void kernel_launch(void* const* d_in, const int* in_sizes, int n_in,
                              void* d_out, int out_size) {
    const float* x     = (const float*)d_in[0];  // (1,16,300000,1)
    const float* w     = (const float*)d_in[1];  // (32,16,27)
    const float* gamma = (const float*)d_in[2];  // (32,)
    const float* beta  = (const float*)d_in[3];  // (32,)
    const void*  neigh = d_in[4];                // (300000,27) i64 or i32
    float*       out   = (float*)d_out;          // (1,32,300000,1)

    detect_kernel<<<1, 1024>>>((const unsigned int*)neigh);
    repack_w_kernel<<<(WSZ + 255) / 256, 256>>>(w);
    transpose_x_kernel<<<(H_ + 255) / 256, 256>>>(x);
    conv_kernel<<<NBLK, TB>>>((const int*)neigh, out);
    stats_kernel<<<COUT, 256>>>(gamma, beta);
    bn_kernel<<<dim3((H_ / 4 + 255) / 256, COUT), 256>>>(out);
}

// round 10
// speedup vs baseline: 2.2285x; 2.0808x over previous
#include <cuda_runtime.h>
#include <cuda_bf16.h>
#include <cstdint>
#include <cstddef>

#define H_    300000
#define CIN   16
#define COUT  32
#define KK    27
#define HB    128
#define TB    128
#define NBLK  ((H_ + HB - 1) / HB)    // 2344
#define NPART (NBLK * 4)              // one partial per (o, block, warp)
#define NIDX  (H_ * KK)
#define ROWB  80                      // A row stride: hi(32B) | lo(32B) | pad(16B)
#define STAGEB (HB * ROWB)            // 10240 B per stage
#define NSTAGE 4

// Scratch (static device globals: allocation-free per harness rules)
__device__ uint4 g_xbf[(size_t)H_ * 4];        // per h: 64B = 16 hi bf16 | 16 lo bf16
__device__ uint2 g_bfrag[KK * 2 * 4 * 32];     // mma B fragments [(k*2+s)*4+nt][lane]
__device__ float g_partials[64 * NPART];
__device__ float g_scale[COUT];
__device__ float g_bias[COUT];
__device__ int   g_is64;

#define MMA_BF16(D, A, B)                                                     \
    asm volatile("mma.sync.aligned.m16n8k16.row.col.f32.bf16.bf16.f32 "       \
                 "{%0,%1,%2,%3}, {%4,%5,%6,%7}, {%8,%9}, {%0,%1,%2,%3};"      \
                 : "+f"((D)[0]), "+f"((D)[1]), "+f"((D)[2]), "+f"((D)[3])     \
                 : "r"((A)[0]), "r"((A)[1]), "r"((A)[2]), "r"((A)[3]),        \
                   "r"((B).x), "r"((B).y))

// ---------------------------------------------------------------------------
// Kernel 0: detect int64 vs int32 neigh (JAX x64 off => i32). Sample odd words.
// ---------------------------------------------------------------------------
__global__ void detect_kernel(const unsigned int* __restrict__ nv) {
    __shared__ int ok;
    if (threadIdx.x == 0) ok = 1;
    __syncthreads();
    unsigned int v = nv[threadIdx.x * 2000 + 1];
    if (v != 0u && v != 0xFFFFFFFFu) ok = 0;
    __syncthreads();
    if (threadIdx.x == 0) g_is64 = ok;
}

// ---------------------------------------------------------------------------
// Kernel 1: build mma B fragments from weights, bf16 hi/lo split.
// B_k[i][o] = w[o][i][k]. Fragment (PTX m16n8k16 B, col): lane l holds
// b0 = {B[2(l%4)][n], B[2(l%4)+1][n]}, b1 = {B[2(l%4)+8][n], B[+9][n]}, n=l/4.
// ---------------------------------------------------------------------------
__global__ void wfrag_kernel(const float* __restrict__ w) {
    int t = blockIdx.x * blockDim.x + threadIdx.x;   // 27*4*32 = 3456
    if (t >= KK * 4 * 32) return;
    int lane = t & 31;
    int nt   = (t >> 5) & 3;
    int k    = t >> 7;
    int o    = nt * 8 + (lane >> 2);
    int i0   = 2 * (lane & 3);
    int ii[4] = {i0, i0 + 1, i0 + 8, i0 + 9};
    unsigned short hi[4], lo[4];
#pragma unroll
    for (int j = 0; j < 4; j++) {
        float vv = w[(o * CIN + ii[j]) * KK + k];
        __nv_bfloat16 bh = __float2bfloat16(vv);
        __nv_bfloat16 bl = __float2bfloat16(vv - __bfloat162float(bh));
        hi[j] = __bfloat16_as_ushort(bh);
        lo[j] = __bfloat16_as_ushort(bl);
    }
    uint2 Hf, Lf;
    Hf.x = (unsigned)hi[0] | ((unsigned)hi[1] << 16);
    Hf.y = (unsigned)hi[2] | ((unsigned)hi[3] << 16);
    Lf.x = (unsigned)lo[0] | ((unsigned)lo[1] << 16);
    Lf.y = (unsigned)lo[2] | ((unsigned)lo[3] << 16);
    g_bfrag[((k * 2 + 0) * 4 + nt) * 32 + lane] = Hf;
    g_bfrag[((k * 2 + 1) * 4 + nt) * 32 + lane] = Lf;
}

// ---------------------------------------------------------------------------
// Kernel 2: transpose + bf16-split x: g_xbf[h] = 64B row [hi[16] | lo[16]].
// ---------------------------------------------------------------------------
__global__ void split_x_kernel(const float* __restrict__ x) {
    int h = blockIdx.x * blockDim.x + threadIdx.x;
    if (h < H_) {
        unsigned int hw[8], lw[8];
#pragma unroll
        for (int t = 0; t < 8; t++) {
            float v0 = x[(size_t)(2 * t) * H_ + h];
            float v1 = x[(size_t)(2 * t + 1) * H_ + h];
            __nv_bfloat16 h0 = __float2bfloat16(v0), h1 = __float2bfloat16(v1);
            __nv_bfloat16 l0 = __float2bfloat16(v0 - __bfloat162float(h0));
            __nv_bfloat16 l1 = __float2bfloat16(v1 - __bfloat162float(h1));
            hw[t] = (unsigned)__bfloat16_as_ushort(h0) |
                    ((unsigned)__bfloat16_as_ushort(h1) << 16);
            lw[t] = (unsigned)__bfloat16_as_ushort(l0) |
                    ((unsigned)__bfloat16_as_ushort(l1) << 16);
        }
        g_xbf[(size_t)h * 4 + 0] = make_uint4(hw[0], hw[1], hw[2], hw[3]);
        g_xbf[(size_t)h * 4 + 1] = make_uint4(hw[4], hw[5], hw[6], hw[7]);
        g_xbf[(size_t)h * 4 + 2] = make_uint4(lw[0], lw[1], lw[2], lw[3]);
        g_xbf[(size_t)h * 4 + 3] = make_uint4(lw[4], lw[5], lw[6], lw[7]);
    }
}

// ---------------------------------------------------------------------------
// Kernel 3: HMMA conv. Per block D[128h,32o] over 27 k16-chunks x 3 split
// GEMMs. Gather via cp.async.cg 16B (zero-fill for invalid idx), 4-stage
// pipeline. A via ldmatrix.x4 (80B row stride: phase-conflict-free).
// B fragments from gmem (L1-hot). Warp w owns rows 32w..32w+31, all 32 o.
// ---------------------------------------------------------------------------
__global__ void __launch_bounds__(TB, 5) conv_kernel(const int* __restrict__ neigh32,
                                                     float* __restrict__ out) {
    __shared__ __align__(128) char Ab[NSTAGE * STAGEB];   // 40960 B

    const int tid  = threadIdx.x;
    const int lane = tid & 31;
    const int wid  = tid >> 5;
    const int h0   = blockIdx.x * HB;
    const int is64 = g_is64;
    const int q     = tid & 3;      // 16B quadrant of a 64B row
    const int rbase = tid >> 2;     // 0..31
    const uint32_t sbase = (uint32_t)__cvta_generic_to_shared(Ab);

    // issue gather of k-chunk into stage k%4 (4 cp.async per thread)
    auto issue = [&](int k) {
        uint32_t dstb = sbase + (k & 3) * STAGEB;
#pragma unroll
        for (int j = 0; j < 4; j++) {
            int r = rbase + 32 * j;
            int h = h0 + r;
            int idx = -1;
            if (h < H_) {
                int gi = h * KK + k;
                idx = neigh32[is64 ? 2 * gi : gi];
            }
            unsigned ok = ((unsigned)idx < (unsigned)H_) ? 16u : 0u;
            const uint4* src = g_xbf + ((size_t)(ok ? idx : 0) * 4 + q);
            uint32_t dst = dstb + r * ROWB + q * 16;
            asm volatile("cp.async.cg.shared.global [%0], [%1], 16, %2;"
                         :: "r"(dst), "l"(src), "r"(ok) : "memory");
        }
        asm volatile("cp.async.commit_group;" ::: "memory");
    };

    // ldmatrix lane addressing (x4: lane -> matrix l/8, row l%8)
    const int rowl = (lane & 7) + ((lane >> 3) & 1) * 8;   // 0-7,8-15,0-7,8-15
    const int byof = (lane >> 4) * 16;                     // i-halves

    float d[2][4][4];
#pragma unroll
    for (int a = 0; a < 2; a++)
#pragma unroll
        for (int b = 0; b < 4; b++)
#pragma unroll
            for (int c = 0; c < 4; c++) d[a][b][c] = 0.f;

    issue(0); issue(1); issue(2);

#pragma unroll 1
    for (int k = 0; k < KK; k++) {
        asm volatile("cp.async.wait_group 2;" ::: "memory");
        __syncthreads();            // chunk k visible; chunk k-1 fully consumed
        if (k + 3 < KK) issue(k + 3);
        else asm volatile("cp.async.commit_group;" ::: "memory");

        const uint32_t bufb = sbase + (k & 3) * STAGEB;
        uint32_t aH[2][4], aL[2][4];
#pragma unroll
        for (int mt = 0; mt < 2; mt++) {
            uint32_t ah = bufb + (wid * 32 + mt * 16 + rowl) * ROWB + byof;
            uint32_t al = ah + 32;
            asm volatile("ldmatrix.sync.aligned.m8n8.x4.shared.b16 {%0,%1,%2,%3}, [%4];"
                         : "=r"(aH[mt][0]), "=r"(aH[mt][1]), "=r"(aH[mt][2]), "=r"(aH[mt][3])
                         : "r"(ah));
            asm volatile("ldmatrix.sync.aligned.m8n8.x4.shared.b16 {%0,%1,%2,%3}, [%4];"
                         : "=r"(aL[mt][0]), "=r"(aL[mt][1]), "=r"(aL[mt][2]), "=r"(aL[mt][3])
                         : "r"(al));
        }
#pragma unroll
        for (int nt = 0; nt < 4; nt++) {
            uint2 bh = g_bfrag[((k * 2 + 0) * 4 + nt) * 32 + lane];
            uint2 bl = g_bfrag[((k * 2 + 1) * 4 + nt) * 32 + lane];
#pragma unroll
            for (int mt = 0; mt < 2; mt++) {
                MMA_BF16(d[mt][nt], aH[mt], bh);   // Ah*Bh
                MMA_BF16(d[mt][nt], aH[mt], bl);   // Ah*Bl
                MMA_BF16(d[mt][nt], aL[mt], bh);   // Al*Bh
            }
        }
    }
    asm volatile("cp.async.wait_group 0;" ::: "memory");

    // Epilogue: D frag lane l: c0,c1 -> row l/4, cols 2(l%4)+{0,1}; c2,c3 -> row+8.
    const int pidx = blockIdx.x * 4 + wid;
#pragma unroll
    for (int nt = 0; nt < 4; nt++) {
        float s0 = 0.f, s1 = 0.f, q0 = 0.f, q1 = 0.f;
#pragma unroll
        for (int mt = 0; mt < 2; mt++) {
            int h  = h0 + wid * 32 + mt * 16 + (lane >> 2);
            int o0 = nt * 8 + 2 * (lane & 3);
            float c0 = d[mt][nt][0], c1 = d[mt][nt][1];
            float c2 = d[mt][nt][2], c3 = d[mt][nt][3];
            if (h < H_) {
                out[(size_t)o0 * H_ + h]       = c0;
                out[(size_t)(o0 + 1) * H_ + h] = c1;
            }
            if (h + 8 < H_) {
                out[(size_t)o0 * H_ + h + 8]       = c2;
                out[(size_t)(o0 + 1) * H_ + h + 8] = c3;
            }
            s0 += c0 + c2; s1 += c1 + c3;
            q0 += c0 * c0 + c2 * c2; q1 += c1 * c1 + c3 * c3;
        }
#pragma unroll
        for (int off = 4; off < 32; off <<= 1) {
            s0 += __shfl_xor_sync(0xffffffffu, s0, off);
            s1 += __shfl_xor_sync(0xffffffffu, s1, off);
            q0 += __shfl_xor_sync(0xffffffffu, q0, off);
            q1 += __shfl_xor_sync(0xffffffffu, q1, off);
        }
        if ((lane >> 2) == 0) {      // lanes 0..3 hold the 8 o's of this nt
            int o0 = nt * 8 + 2 * lane;
            g_partials[o0 * NPART + pidx]            = s0;
            g_partials[(o0 + 1) * NPART + pidx]      = s1;
            g_partials[(32 + o0) * NPART + pidx]     = q0;
            g_partials[(32 + o0 + 1) * NPART + pidx] = q1;
        }
    }
}

// ---------------------------------------------------------------------------
// Kernel 4: one block per channel; deterministic fp64 reduction -> scale/bias.
// ---------------------------------------------------------------------------
__global__ void stats_kernel(const float* __restrict__ gamma,
                             const float* __restrict__ beta) {
    const int o = blockIdx.x;
    double s1 = 0.0, s2 = 0.0;
    for (int b = threadIdx.x; b < NPART; b += blockDim.x) {
        s1 += (double)g_partials[o * NPART + b];
        s2 += (double)g_partials[(32 + o) * NPART + b];
    }
    __shared__ double r1[256], r2[256];
    r1[threadIdx.x] = s1;
    r2[threadIdx.x] = s2;
    __syncthreads();
    for (int sft = 128; sft > 0; sft >>= 1) {
        if (threadIdx.x < sft) {
            r1[threadIdx.x] += r1[threadIdx.x + sft];
            r2[threadIdx.x] += r2[threadIdx.x + sft];
        }
        __syncthreads();
    }
    if (threadIdx.x == 0) {
        double mean = r1[0] / (double)H_;
        double var  = r2[0] / (double)H_ - mean * mean;
        float rstd  = rsqrtf((float)(var + 1e-5));
        float sc    = rstd * gamma[o];
        g_scale[o]  = sc;
        g_bias[o]   = beta[o] - (float)mean * sc;
    }
}

// ---------------------------------------------------------------------------
// Kernel 5: normalize in place (float4; H % 4 == 0).
// ---------------------------------------------------------------------------
__global__ void bn_kernel(float* __restrict__ out) {
    const int o = blockIdx.y;
    const int t = blockIdx.x * blockDim.x + threadIdx.x;
    const float sc = g_scale[o], bi = g_bias[o];
    float4* p = reinterpret_cast<float4*>(out + (size_t)o * H_);
    if (t < H_ / 4) {
        float4 v = p[t];
        v.x = v.x * sc + bi;
        v.y = v.y * sc + bi;
        v.z = v.z * sc + bi;
        v.w = v.w * sc + bi;
        p[t] = v;
    }
}

// ---------------------------------------------------------------------------
extern "C" void kernel_launch(void* const* d_in, const int* in_sizes, int n_in,
                              void* d_out, int out_size) {
    const float* x     = (const float*)d_in[0];  // (1,16,300000,1)
    const float* w     = (const float*)d_in[1];  // (32,16,27)
    const float* gamma = (const float*)d_in[2];  // (32,)
    const float* beta  = (const float*)d_in[3];  // (32,)
    const void*  neigh = d_in[4];                // (300000,27) i64 or i32
    float*       out   = (float*)d_out;          // (1,32,300000,1)

    cudaFuncSetAttribute(conv_kernel,
                         cudaFuncAttributePreferredSharedMemoryCarveout,
                         cudaSharedmemCarveoutMaxShared);

    detect_kernel<<<1, 1024>>>((const unsigned int*)neigh);
    wfrag_kernel<<<(KK * 4 * 32 + 255) / 256, 256>>>(w);
    split_x_kernel<<<(H_ + 255) / 256, 256>>>(x);
    conv_kernel<<<NBLK, TB>>>((const int*)neigh, out);
    stats_kernel<<<COUT, 256>>>(gamma, beta);
    bn_kernel<<<dim3((H_ / 4 + 255) / 256, COUT), 256>>>(out);
}

// round 11
// speedup vs baseline: 2.3835x; 1.0695x over previous
#include <cuda_runtime.h>
#include <cuda_bf16.h>
#include <cstdint>
#include <cstddef>

#define H_    300000
#define CIN   16
#define COUT  32
#define KK    27
#define HB    128
#define TB    128
#define NBLK  ((H_ + HB - 1) / HB)    // 2344
#define NPART (NBLK * 4)              // one partial per (o, block, warp)
#define NIDX  (H_ * KK)
#define ROWB  80                      // A row stride: hi(32B) | lo(32B) | pad(16B)
#define STAGEB (HB * ROWB)            // 10240 B per stage
#define NSTAGE 3

// Scratch (static device globals: allocation-free per harness rules)
__device__ uint4 g_xbf[(size_t)H_ * 4];        // per h: 64B = 16 hi bf16 | 16 lo bf16
__device__ uint2 g_bfrag[KK * 2 * 4 * 32];     // mma B fragments [(k*2+s)*4+nt][lane]
__device__ float g_partials[64 * NPART];
__device__ float g_scale[COUT];
__device__ float g_bias[COUT];
__device__ int   g_is64;

#define MMA_BF16(D, A, B)                                                     \
    asm volatile("mma.sync.aligned.m16n8k16.row.col.f32.bf16.bf16.f32 "       \
                 "{%0,%1,%2,%3}, {%4,%5,%6,%7}, {%8,%9}, {%0,%1,%2,%3};"      \
                 : "+f"((D)[0]), "+f"((D)[1]), "+f"((D)[2]), "+f"((D)[3])     \
                 : "r"((A)[0]), "r"((A)[1]), "r"((A)[2]), "r"((A)[3]),        \
                   "r"((B).x), "r"((B).y))

// ---------------------------------------------------------------------------
// Kernel 0: detect int64 vs int32 neigh (JAX x64 off => i32). Sample odd words.
// ---------------------------------------------------------------------------
__global__ void detect_kernel(const unsigned int* __restrict__ nv) {
    __shared__ int ok;
    if (threadIdx.x == 0) ok = 1;
    __syncthreads();
    unsigned int v = nv[threadIdx.x * 2000 + 1];
    if (v != 0u && v != 0xFFFFFFFFu) ok = 0;
    __syncthreads();
    if (threadIdx.x == 0) g_is64 = ok;
}

// ---------------------------------------------------------------------------
// Kernel 1: build mma B fragments from weights, bf16 hi/lo split.
// B_k[i][o] = w[o][i][k]. Fragment (PTX m16n8k16 B, col): lane l holds
// b0 = {B[2(l%4)][n], B[2(l%4)+1][n]}, b1 = {B[2(l%4)+8][n], B[+9][n]}, n=l/4.
// ---------------------------------------------------------------------------
__global__ void wfrag_kernel(const float* __restrict__ w) {
    int t = blockIdx.x * blockDim.x + threadIdx.x;   // 27*4*32 = 3456
    if (t >= KK * 4 * 32) return;
    int lane = t & 31;
    int nt   = (t >> 5) & 3;
    int k    = t >> 7;
    int o    = nt * 8 + (lane >> 2);
    int i0   = 2 * (lane & 3);
    int ii[4] = {i0, i0 + 1, i0 + 8, i0 + 9};
    unsigned short hi[4], lo[4];
#pragma unroll
    for (int j = 0; j < 4; j++) {
        float vv = w[(o * CIN + ii[j]) * KK + k];
        __nv_bfloat16 bh = __float2bfloat16(vv);
        __nv_bfloat16 bl = __float2bfloat16(vv - __bfloat162float(bh));
        hi[j] = __bfloat16_as_ushort(bh);
        lo[j] = __bfloat16_as_ushort(bl);
    }
    uint2 Hf, Lf;
    Hf.x = (unsigned)hi[0] | ((unsigned)hi[1] << 16);
    Hf.y = (unsigned)hi[2] | ((unsigned)hi[3] << 16);
    Lf.x = (unsigned)lo[0] | ((unsigned)lo[1] << 16);
    Lf.y = (unsigned)lo[2] | ((unsigned)lo[3] << 16);
    g_bfrag[((k * 2 + 0) * 4 + nt) * 32 + lane] = Hf;
    g_bfrag[((k * 2 + 1) * 4 + nt) * 32 + lane] = Lf;
}

// ---------------------------------------------------------------------------
// Kernel 2: transpose + bf16-split x: g_xbf[h] = 64B row [hi[16] | lo[16]].
// ---------------------------------------------------------------------------
__global__ void split_x_kernel(const float* __restrict__ x) {
    int h = blockIdx.x * blockDim.x + threadIdx.x;
    if (h < H_) {
        unsigned int hw[8], lw[8];
#pragma unroll
        for (int t = 0; t < 8; t++) {
            float v0 = x[(size_t)(2 * t) * H_ + h];
            float v1 = x[(size_t)(2 * t + 1) * H_ + h];
            __nv_bfloat16 h0 = __float2bfloat16(v0), h1 = __float2bfloat16(v1);
            __nv_bfloat16 l0 = __float2bfloat16(v0 - __bfloat162float(h0));
            __nv_bfloat16 l1 = __float2bfloat16(v1 - __bfloat162float(h1));
            hw[t] = (unsigned)__bfloat16_as_ushort(h0) |
                    ((unsigned)__bfloat16_as_ushort(h1) << 16);
            lw[t] = (unsigned)__bfloat16_as_ushort(l0) |
                    ((unsigned)__bfloat16_as_ushort(l1) << 16);
        }
        g_xbf[(size_t)h * 4 + 0] = make_uint4(hw[0], hw[1], hw[2], hw[3]);
        g_xbf[(size_t)h * 4 + 1] = make_uint4(hw[4], hw[5], hw[6], hw[7]);
        g_xbf[(size_t)h * 4 + 2] = make_uint4(lw[0], lw[1], lw[2], lw[3]);
        g_xbf[(size_t)h * 4 + 3] = make_uint4(lw[4], lw[5], lw[6], lw[7]);
    }
}

// ---------------------------------------------------------------------------
// Kernel 3: HMMA conv, warp-local 3-stage cp.async pipeline (NO block barrier
// in the mainloop). Warp w gathers AND consumes rows 32w..32w+31 only, so
// stage sync is cp.async.wait_group + __syncwarp. 27 k16-chunks x 3 split
// GEMMs (Ah·Bh + Ah·Bl + Al·Bh). B fragments from gmem (L1-hot).
// ---------------------------------------------------------------------------
__global__ void __launch_bounds__(TB, 6) conv_kernel(const int* __restrict__ neigh32,
                                                     float* __restrict__ out) {
    __shared__ __align__(128) char Ab[NSTAGE * STAGEB];   // 30720 B

    const int tid  = threadIdx.x;
    const int lane = tid & 31;
    const int wid  = tid >> 5;
    const int h0   = blockIdx.x * HB;
    const int is64 = g_is64;
    const uint32_t sbase = (uint32_t)__cvta_generic_to_shared(Ab);

    // Warp-local gather mapping: lane -> q = 16B quadrant, rl + 8j = row in warp.
    const int q  = lane & 3;
    const int rl = lane >> 2;       // 0..7

    // issue gather of k-chunk into stage k%3 (4 cp.async per thread, own warp's rows)
    auto issue = [&](int k) {
        uint32_t dstb = sbase + (k % NSTAGE) * STAGEB;
#pragma unroll
        for (int j = 0; j < 4; j++) {
            int r = wid * 32 + rl + 8 * j;    // block-row, within this warp's 32
            int h = h0 + r;
            int idx = -1;
            if (h < H_) {
                int gi = h * KK + k;
                idx = neigh32[is64 ? 2 * gi : gi];
            }
            unsigned ok = ((unsigned)idx < (unsigned)H_) ? 16u : 0u;
            const uint4* src = g_xbf + ((size_t)(ok ? idx : 0) * 4 + q);
            uint32_t dst = dstb + r * ROWB + q * 16;
            asm volatile("cp.async.cg.shared.global [%0], [%1], 16, %2;"
                         :: "r"(dst), "l"(src), "r"(ok) : "memory");
        }
        asm volatile("cp.async.commit_group;" ::: "memory");
    };

    // ldmatrix lane addressing (x4: lane -> matrix l/8, row l%8)
    const int rowl = (lane & 7) + ((lane >> 3) & 1) * 8;   // 0-7,8-15,0-7,8-15
    const int byof = (lane >> 4) * 16;                     // i-halves

    float d[2][4][4];
#pragma unroll
    for (int a = 0; a < 2; a++)
#pragma unroll
        for (int b = 0; b < 4; b++)
#pragma unroll
            for (int c = 0; c < 4; c++) d[a][b][c] = 0.f;

    issue(0); issue(1);

#pragma unroll 1
    for (int k = 0; k < KK; k++) {
        asm volatile("cp.async.wait_group 1;" ::: "memory");   // chunk k done
        __syncwarp();
        if (k + 2 < KK) issue(k + 2);
        else asm volatile("cp.async.commit_group;" ::: "memory");

        const uint32_t bufb = sbase + (k % NSTAGE) * STAGEB;
        uint32_t aH[2][4], aL[2][4];
#pragma unroll
        for (int mt = 0; mt < 2; mt++) {
            uint32_t ah = bufb + (wid * 32 + mt * 16 + rowl) * ROWB + byof;
            uint32_t al = ah + 32;
            asm volatile("ldmatrix.sync.aligned.m8n8.x4.shared.b16 {%0,%1,%2,%3}, [%4];"
                         : "=r"(aH[mt][0]), "=r"(aH[mt][1]), "=r"(aH[mt][2]), "=r"(aH[mt][3])
                         : "r"(ah));
            asm volatile("ldmatrix.sync.aligned.m8n8.x4.shared.b16 {%0,%1,%2,%3}, [%4];"
                         : "=r"(aL[mt][0]), "=r"(aL[mt][1]), "=r"(aL[mt][2]), "=r"(aL[mt][3])
                         : "r"(al));
        }
#pragma unroll
        for (int nt = 0; nt < 4; nt++) {
            uint2 bh = g_bfrag[((k * 2 + 0) * 4 + nt) * 32 + lane];
            uint2 bl = g_bfrag[((k * 2 + 1) * 4 + nt) * 32 + lane];
#pragma unroll
            for (int mt = 0; mt < 2; mt++) {
                MMA_BF16(d[mt][nt], aH[mt], bh);   // Ah*Bh
                MMA_BF16(d[mt][nt], aH[mt], bl);   // Ah*Bl
                MMA_BF16(d[mt][nt], aL[mt], bh);   // Al*Bh
            }
        }
        __syncwarp();   // all lanes done reading stage k before it is re-issued
    }
    asm volatile("cp.async.wait_group 0;" ::: "memory");

    // Epilogue: D frag lane l: c0,c1 -> row l/4, cols 2(l%4)+{0,1}; c2,c3 -> row+8.
    const int pidx = blockIdx.x * 4 + wid;
#pragma unroll
    for (int nt = 0; nt < 4; nt++) {
        float s0 = 0.f, s1 = 0.f, q0 = 0.f, q1 = 0.f;
#pragma unroll
        for (int mt = 0; mt < 2; mt++) {
            int h  = h0 + wid * 32 + mt * 16 + (lane >> 2);
            int o0 = nt * 8 + 2 * (lane & 3);
            float c0 = d[mt][nt][0], c1 = d[mt][nt][1];
            float c2 = d[mt][nt][2], c3 = d[mt][nt][3];
            if (h < H_) {
                out[(size_t)o0 * H_ + h]       = c0;
                out[(size_t)(o0 + 1) * H_ + h] = c1;
            }
            if (h + 8 < H_) {
                out[(size_t)o0 * H_ + h + 8]       = c2;
                out[(size_t)(o0 + 1) * H_ + h + 8] = c3;
            }
            s0 += c0 + c2; s1 += c1 + c3;
            q0 += c0 * c0 + c2 * c2; q1 += c1 * c1 + c3 * c3;
        }
#pragma unroll
        for (int off = 4; off < 32; off <<= 1) {
            s0 += __shfl_xor_sync(0xffffffffu, s0, off);
            s1 += __shfl_xor_sync(0xffffffffu, s1, off);
            q0 += __shfl_xor_sync(0xffffffffu, q0, off);
            q1 += __shfl_xor_sync(0xffffffffu, q1, off);
        }
        if ((lane >> 2) == 0) {      // lanes 0..3 hold the 8 o's of this nt
            int o0 = nt * 8 + 2 * lane;
            g_partials[o0 * NPART + pidx]            = s0;
            g_partials[(o0 + 1) * NPART + pidx]      = s1;
            g_partials[(32 + o0) * NPART + pidx]     = q0;
            g_partials[(32 + o0 + 1) * NPART + pidx] = q1;
        }
    }
}

// ---------------------------------------------------------------------------
// Kernel 4: one block per channel; deterministic fp64 reduction -> scale/bias.
// ---------------------------------------------------------------------------
__global__ void stats_kernel(const float* __restrict__ gamma,
                             const float* __restrict__ beta) {
    const int o = blockIdx.x;
    double s1 = 0.0, s2 = 0.0;
    for (int b = threadIdx.x; b < NPART; b += blockDim.x) {
        s1 += (double)g_partials[o * NPART + b];
        s2 += (double)g_partials[(32 + o) * NPART + b];
    }
    __shared__ double r1[256], r2[256];
    r1[threadIdx.x] = s1;
    r2[threadIdx.x] = s2;
    __syncthreads();
    for (int sft = 128; sft > 0; sft >>= 1) {
        if (threadIdx.x < sft) {
            r1[threadIdx.x] += r1[threadIdx.x + sft];
            r2[threadIdx.x] += r2[threadIdx.x + sft];
        }
        __syncthreads();
    }
    if (threadIdx.x == 0) {
        double mean = r1[0] / (double)H_;
        double var  = r2[0] / (double)H_ - mean * mean;
        float rstd  = rsqrtf((float)(var + 1e-5));
        float sc    = rstd * gamma[o];
        g_scale[o]  = sc;
        g_bias[o]   = beta[o] - (float)mean * sc;
    }
}

// ---------------------------------------------------------------------------
// Kernel 5: normalize in place (float4; H % 4 == 0).
// ---------------------------------------------------------------------------
__global__ void bn_kernel(float* __restrict__ out) {
    const int o = blockIdx.y;
    const int t = blockIdx.x * blockDim.x + threadIdx.x;
    const float sc = g_scale[o], bi = g_bias[o];
    float4* p = reinterpret_cast<float4*>(out + (size_t)o * H_);
    if (t < H_ / 4) {
        float4 v = p[t];
        v.x = v.x * sc + bi;
        v.y = v.y * sc + bi;
        v.z = v.z * sc + bi;
        v.w = v.w * sc + bi;
        p[t] = v;
    }
}

// ---------------------------------------------------------------------------
extern "C" void kernel_launch(void* const* d_in, const int* in_sizes, int n_in,
                              void* d_out, int out_size) {
    const float* x     = (const float*)d_in[0];  // (1,16,300000,1)
    const float* w     = (const float*)d_in[1];  // (32,16,27)
    const float* gamma = (const float*)d_in[2];  // (32,)
    const float* beta  = (const float*)d_in[3];  // (32,)
    const void*  neigh = d_in[4];                // (300000,27) i64 or i32
    float*       out   = (float*)d_out;          // (1,32,300000,1)

    cudaFuncSetAttribute(conv_kernel,
                         cudaFuncAttributePreferredSharedMemoryCarveout,
                         cudaSharedmemCarveoutMaxShared);

    detect_kernel<<<1, 1024>>>((const unsigned int*)neigh);
    wfrag_kernel<<<(KK * 4 * 32 + 255) / 256, 256>>>(w);
    split_x_kernel<<<(H_ + 255) / 256, 256>>>(x);
    conv_kernel<<<NBLK, TB>>>((const int*)neigh, out);
    stats_kernel<<<COUT, 256>>>(gamma, beta);
    bn_kernel<<<dim3((H_ / 4 + 255) / 256, COUT), 256>>>(out);
}

// round 12
// speedup vs baseline: 2.4206x; 1.0156x over previous
#include <cuda_runtime.h>
#include <cuda_bf16.h>
#include <cstdint>
#include <cstddef>

#define H_    300000
#define CIN   16
#define COUT  32
#define KK    27
#define HB    128
#define TB    128
#define NBLK  ((H_ + HB - 1) / HB)    // 2344
#define NPART (NBLK * 4)              // one partial per (o, block, warp)
#define NIDX  (H_ * KK)
#define ROWB  80                      // A row stride: hi(32B) | lo(32B) | pad(16B)
#define STAGEB (HB * ROWB)            // 10240 B per stage
#define NSTAGE 4
#define SCHUNK 8                      // stats reduction chunks per row

// Scratch (static device globals: allocation-free per harness rules)
__device__ uint4  g_xbf[(size_t)H_ * 4];       // per h: 64B = 16 hi bf16 | 16 lo bf16
__device__ uint2  g_bfrag[KK * 2 * 4 * 32];    // mma B fragments [(k*2+s)*4+nt][lane]
__device__ float  g_partials[64 * NPART];
__device__ double g_red[64 * SCHUNK];          // stats stage-1 output
__device__ float  g_scale[COUT];
__device__ float  g_bias[COUT];
__device__ int    g_is64;

#define MMA_BF16(D, A, B)                                                     \
    asm volatile("mma.sync.aligned.m16n8k16.row.col.f32.bf16.bf16.f32 "       \
                 "{%0,%1,%2,%3}, {%4,%5,%6,%7}, {%8,%9}, {%0,%1,%2,%3};"      \
                 : "+f"((D)[0]), "+f"((D)[1]), "+f"((D)[2]), "+f"((D)[3])     \
                 : "r"((A)[0]), "r"((A)[1]), "r"((A)[2]), "r"((A)[3]),        \
                   "r"((B).x), "r"((B).y))

// ---------------------------------------------------------------------------
// Kernel 0: detect int64 vs int32 neigh (JAX x64 off => i32). Sample odd words.
// ---------------------------------------------------------------------------
__global__ void detect_kernel(const unsigned int* __restrict__ nv) {
    __shared__ int ok;
    if (threadIdx.x == 0) ok = 1;
    __syncthreads();
    unsigned int v = nv[threadIdx.x * 2000 + 1];
    if (v != 0u && v != 0xFFFFFFFFu) ok = 0;
    __syncthreads();
    if (threadIdx.x == 0) g_is64 = ok;
}

// ---------------------------------------------------------------------------
// Kernel 1: build mma B fragments from weights, bf16 hi/lo split.
// B_k[i][o] = w[o][i][k]. Fragment (PTX m16n8k16 B, col): lane l holds
// b0 = {B[2(l%4)][n], B[2(l%4)+1][n]}, b1 = {B[2(l%4)+8][n], B[+9][n]}, n=l/4.
// ---------------------------------------------------------------------------
__global__ void wfrag_kernel(const float* __restrict__ w) {
    int t = blockIdx.x * blockDim.x + threadIdx.x;   // 27*4*32 = 3456
    if (t >= KK * 4 * 32) return;
    int lane = t & 31;
    int nt   = (t >> 5) & 3;
    int k    = t >> 7;
    int o    = nt * 8 + (lane >> 2);
    int i0   = 2 * (lane & 3);
    int ii[4] = {i0, i0 + 1, i0 + 8, i0 + 9};
    unsigned short hi[4], lo[4];
#pragma unroll
    for (int j = 0; j < 4; j++) {
        float vv = w[(o * CIN + ii[j]) * KK + k];
        __nv_bfloat16 bh = __float2bfloat16(vv);
        __nv_bfloat16 bl = __float2bfloat16(vv - __bfloat162float(bh));
        hi[j] = __bfloat16_as_ushort(bh);
        lo[j] = __bfloat16_as_ushort(bl);
    }
    uint2 Hf, Lf;
    Hf.x = (unsigned)hi[0] | ((unsigned)hi[1] << 16);
    Hf.y = (unsigned)hi[2] | ((unsigned)hi[3] << 16);
    Lf.x = (unsigned)lo[0] | ((unsigned)lo[1] << 16);
    Lf.y = (unsigned)lo[2] | ((unsigned)lo[3] << 16);
    g_bfrag[((k * 2 + 0) * 4 + nt) * 32 + lane] = Hf;
    g_bfrag[((k * 2 + 1) * 4 + nt) * 32 + lane] = Lf;
}

// ---------------------------------------------------------------------------
// Kernel 2: transpose + bf16-split x: g_xbf[h] = 64B row [hi[16] | lo[16]].
// ---------------------------------------------------------------------------
__global__ void split_x_kernel(const float* __restrict__ x) {
    int h = blockIdx.x * blockDim.x + threadIdx.x;
    if (h < H_) {
        unsigned int hw[8], lw[8];
#pragma unroll
        for (int t = 0; t < 8; t++) {
            float v0 = x[(size_t)(2 * t) * H_ + h];
            float v1 = x[(size_t)(2 * t + 1) * H_ + h];
            __nv_bfloat16 h0 = __float2bfloat16(v0), h1 = __float2bfloat16(v1);
            __nv_bfloat16 l0 = __float2bfloat16(v0 - __bfloat162float(h0));
            __nv_bfloat16 l1 = __float2bfloat16(v1 - __bfloat162float(h1));
            hw[t] = (unsigned)__bfloat16_as_ushort(h0) |
                    ((unsigned)__bfloat16_as_ushort(h1) << 16);
            lw[t] = (unsigned)__bfloat16_as_ushort(l0) |
                    ((unsigned)__bfloat16_as_ushort(l1) << 16);
        }
        g_xbf[(size_t)h * 4 + 0] = make_uint4(hw[0], hw[1], hw[2], hw[3]);
        g_xbf[(size_t)h * 4 + 1] = make_uint4(hw[4], hw[5], hw[6], hw[7]);
        g_xbf[(size_t)h * 4 + 2] = make_uint4(lw[0], lw[1], lw[2], lw[3]);
        g_xbf[(size_t)h * 4 + 3] = make_uint4(lw[4], lw[5], lw[6], lw[7]);
    }
}

// ---------------------------------------------------------------------------
// Kernel 3: HMMA conv, warp-local 4-stage cp.async pipeline (no block barrier
// in the mainloop). Warp w gathers AND consumes rows 32w..32w+31; stage sync
// is cp.async.wait_group 2 + __syncwarp (prefetch depth 3 = 12 outstanding
// gathers/warp). 27 k16-chunks x 3 split GEMMs (Ah·Bh + Ah·Bl + Al·Bh).
// ---------------------------------------------------------------------------
__global__ void __launch_bounds__(TB, 5) conv_kernel(const int* __restrict__ neigh32,
                                                     float* __restrict__ out) {
    __shared__ __align__(128) char Ab[NSTAGE * STAGEB];   // 40960 B

    const int tid  = threadIdx.x;
    const int lane = tid & 31;
    const int wid  = tid >> 5;
    const int h0   = blockIdx.x * HB;
    const int is64 = g_is64;
    const uint32_t sbase = (uint32_t)__cvta_generic_to_shared(Ab);

    // Warp-local gather mapping: lane -> q = 16B quadrant, rl + 8j = row in warp.
    const int q  = lane & 3;
    const int rl = lane >> 2;       // 0..7

    // issue gather of k-chunk into stage k%4 (4 cp.async per thread, own warp's rows)
    auto issue = [&](int k) {
        uint32_t dstb = sbase + (k & (NSTAGE - 1)) * STAGEB;
#pragma unroll
        for (int j = 0; j < 4; j++) {
            int r = wid * 32 + rl + 8 * j;    // block-row, within this warp's 32
            int h = h0 + r;
            int idx = -1;
            if (h < H_) {
                int gi = h * KK + k;
                idx = neigh32[is64 ? 2 * gi : gi];
            }
            unsigned ok = ((unsigned)idx < (unsigned)H_) ? 16u : 0u;
            const uint4* src = g_xbf + ((size_t)(ok ? idx : 0) * 4 + q);
            uint32_t dst = dstb + r * ROWB + q * 16;
            asm volatile("cp.async.cg.shared.global [%0], [%1], 16, %2;"
                         :: "r"(dst), "l"(src), "r"(ok) : "memory");
        }
        asm volatile("cp.async.commit_group;" ::: "memory");
    };

    // ldmatrix lane addressing (x4: lane -> matrix l/8, row l%8)
    const int rowl = (lane & 7) + ((lane >> 3) & 1) * 8;   // 0-7,8-15,0-7,8-15
    const int byof = (lane >> 4) * 16;                     // i-halves

    float d[2][4][4];
#pragma unroll
    for (int a = 0; a < 2; a++)
#pragma unroll
        for (int b = 0; b < 4; b++)
#pragma unroll
            for (int c = 0; c < 4; c++) d[a][b][c] = 0.f;

    issue(0); issue(1); issue(2);

#pragma unroll 1
    for (int k = 0; k < KK; k++) {
        asm volatile("cp.async.wait_group 2;" ::: "memory");   // chunk k done
        __syncwarp();
        if (k + 3 < KK) issue(k + 3);
        else asm volatile("cp.async.commit_group;" ::: "memory");

        const uint32_t bufb = sbase + (k & (NSTAGE - 1)) * STAGEB;
        uint32_t aH[2][4], aL[2][4];
#pragma unroll
        for (int mt = 0; mt < 2; mt++) {
            uint32_t ah = bufb + (wid * 32 + mt * 16 + rowl) * ROWB + byof;
            uint32_t al = ah + 32;
            asm volatile("ldmatrix.sync.aligned.m8n8.x4.shared.b16 {%0,%1,%2,%3}, [%4];"
                         : "=r"(aH[mt][0]), "=r"(aH[mt][1]), "=r"(aH[mt][2]), "=r"(aH[mt][3])
                         : "r"(ah));
            asm volatile("ldmatrix.sync.aligned.m8n8.x4.shared.b16 {%0,%1,%2,%3}, [%4];"
                         : "=r"(aL[mt][0]), "=r"(aL[mt][1]), "=r"(aL[mt][2]), "=r"(aL[mt][3])
                         : "r"(al));
        }
#pragma unroll
        for (int nt = 0; nt < 4; nt++) {
            uint2 bh = g_bfrag[((k * 2 + 0) * 4 + nt) * 32 + lane];
            uint2 bl = g_bfrag[((k * 2 + 1) * 4 + nt) * 32 + lane];
#pragma unroll
            for (int mt = 0; mt < 2; mt++) {
                MMA_BF16(d[mt][nt], aH[mt], bh);   // Ah*Bh
                MMA_BF16(d[mt][nt], aH[mt], bl);   // Ah*Bl
                MMA_BF16(d[mt][nt], aL[mt], bh);   // Al*Bh
            }
        }
        __syncwarp();   // all lanes done reading stage k before it is re-issued
    }
    asm volatile("cp.async.wait_group 0;" ::: "memory");

    // Epilogue: D frag lane l: c0,c1 -> row l/4, cols 2(l%4)+{0,1}; c2,c3 -> row+8.
    const int pidx = blockIdx.x * 4 + wid;
#pragma unroll
    for (int nt = 0; nt < 4; nt++) {
        float s0 = 0.f, s1 = 0.f, q0 = 0.f, q1 = 0.f;
#pragma unroll
        for (int mt = 0; mt < 2; mt++) {
            int h  = h0 + wid * 32 + mt * 16 + (lane >> 2);
            int o0 = nt * 8 + 2 * (lane & 3);
            float c0 = d[mt][nt][0], c1 = d[mt][nt][1];
            float c2 = d[mt][nt][2], c3 = d[mt][nt][3];
            if (h < H_) {
                out[(size_t)o0 * H_ + h]       = c0;
                out[(size_t)(o0 + 1) * H_ + h] = c1;
            }
            if (h + 8 < H_) {
                out[(size_t)o0 * H_ + h + 8]       = c2;
                out[(size_t)(o0 + 1) * H_ + h + 8] = c3;
            }
            s0 += c0 + c2; s1 += c1 + c3;
            q0 += c0 * c0 + c2 * c2; q1 += c1 * c1 + c3 * c3;
        }
#pragma unroll
        for (int off = 4; off < 32; off <<= 1) {
            s0 += __shfl_xor_sync(0xffffffffu, s0, off);
            s1 += __shfl_xor_sync(0xffffffffu, s1, off);
            q0 += __shfl_xor_sync(0xffffffffu, q0, off);
            q1 += __shfl_xor_sync(0xffffffffu, q1, off);
        }
        if ((lane >> 2) == 0) {      // lanes 0..3 hold the 8 o's of this nt
            int o0 = nt * 8 + 2 * lane;
            g_partials[o0 * NPART + pidx]            = s0;
            g_partials[(o0 + 1) * NPART + pidx]      = s1;
            g_partials[(32 + o0) * NPART + pidx]     = q0;
            g_partials[(32 + o0 + 1) * NPART + pidx] = q1;
        }
    }
}

// ---------------------------------------------------------------------------
// Kernel 4a: stats stage 1 — 64 rows x SCHUNK chunks; deterministic fp64 tree.
// ---------------------------------------------------------------------------
__global__ void stats1_kernel() {
    const int row   = blockIdx.x;        // 0..63
    const int chunk = blockIdx.y;        // 0..SCHUNK-1
    const int per   = (NPART + SCHUNK - 1) / SCHUNK;   // 1172
    const int b0    = chunk * per;
    const int b1    = (b0 + per < NPART) ? b0 + per : NPART;
    double s = 0.0;
    for (int b = b0 + threadIdx.x; b < b1; b += blockDim.x)
        s += (double)g_partials[row * NPART + b];
    __shared__ double r[256];
    r[threadIdx.x] = s;
    __syncthreads();
    for (int sft = 128; sft > 0; sft >>= 1) {
        if (threadIdx.x < sft) r[threadIdx.x] += r[threadIdx.x + sft];
        __syncthreads();
    }
    if (threadIdx.x == 0) g_red[row * SCHUNK + chunk] = r[0];
}

// ---------------------------------------------------------------------------
// Kernel 4b: stats stage 2 — fold SCHUNK chunk-sums per channel -> scale/bias.
// ---------------------------------------------------------------------------
__global__ void stats2_kernel(const float* __restrict__ gamma,
                              const float* __restrict__ beta) {
    const int o = blockIdx.x;
    if (threadIdx.x == 0) {
        double s1 = 0.0, s2 = 0.0;
#pragma unroll
        for (int c = 0; c < SCHUNK; c++) {
            s1 += g_red[o * SCHUNK + c];
            s2 += g_red[(32 + o) * SCHUNK + c];
        }
        double mean = s1 / (double)H_;
        double var  = s2 / (double)H_ - mean * mean;
        float rstd  = rsqrtf((float)(var + 1e-5));
        float sc    = rstd * gamma[o];
        g_scale[o]  = sc;
        g_bias[o]   = beta[o] - (float)mean * sc;
    }
}

// ---------------------------------------------------------------------------
// Kernel 5: normalize in place (float4; H % 4 == 0).
// ---------------------------------------------------------------------------
__global__ void bn_kernel(float* __restrict__ out) {
    const int o = blockIdx.y;
    const int t = blockIdx.x * blockDim.x + threadIdx.x;
    const float sc = g_scale[o], bi = g_bias[o];
    float4* p = reinterpret_cast<float4*>(out + (size_t)o * H_);
    if (t < H_ / 4) {
        float4 v = p[t];
        v.x = v.x * sc + bi;
        v.y = v.y * sc + bi;
        v.z = v.z * sc + bi;
        v.w = v.w * sc + bi;
        p[t] = v;
    }
}

// ---------------------------------------------------------------------------
extern "C" void kernel_launch(void* const* d_in, const int* in_sizes, int n_in,
                              void* d_out, int out_size) {
    const float* x     = (const float*)d_in[0];  // (1,16,300000,1)
    const float* w     = (const float*)d_in[1];  // (32,16,27)
    const float* gamma = (const float*)d_in[2];  // (32,)
    const float* beta  = (const float*)d_in[3];  // (32,)
    const void*  neigh = d_in[4];                // (300000,27) i64 or i32
    float*       out   = (float*)d_out;          // (1,32,300000,1)

    cudaFuncSetAttribute(conv_kernel,
                         cudaFuncAttributePreferredSharedMemoryCarveout,
                         cudaSharedmemCarveoutMaxShared);

    detect_kernel<<<1, 1024>>>((const unsigned int*)neigh);
    wfrag_kernel<<<(KK * 4 * 32 + 255) / 256, 256>>>(w);
    split_x_kernel<<<(H_ + 255) / 256, 256>>>(x);
    conv_kernel<<<NBLK, TB>>>((const int*)neigh, out);
    stats1_kernel<<<dim3(64, SCHUNK), 256>>>();
    stats2_kernel<<<COUT, 32>>>(gamma, beta);
    bn_kernel<<<dim3((H_ / 4 + 255) / 256, COUT), 256>>>(out);
}

// round 13
// speedup vs baseline: 2.4911x; 1.0291x over previous
#include <cuda_runtime.h>
#include <cuda_bf16.h>
#include <cstdint>
#include <cstddef>

#define H_    300000
#define CIN   16
#define COUT  32
#define KK    27
#define HB    128
#define TB    128
#define NBLK  ((H_ + HB - 1) / HB)    // 2344
#define NPART (NBLK * 4)              // one partial per (o, block, warp)
#define NIDX  (H_ * KK)
#define ROWB  80                      // A row stride: hi(32B) | lo(32B) | pad(16B)
#define STAGEB (HB * ROWB)            // 10240 B per stage
#define NSTAGE 3
#define SCHUNK 8                      // stats reduction chunks per row

// Scratch (static device globals: allocation-free per harness rules)
__device__ uint4  g_xbf[(size_t)H_ * 4];       // per h: 64B = 16 hi bf16 | 16 lo bf16
__device__ uint2  g_bfrag[KK * 2 * 4 * 32];    // mma B fragments [(k*2+s)*4+nt][lane]
__device__ float  g_partials[64 * NPART];
__device__ double g_red[64 * SCHUNK];          // stats stage-1 output
__device__ float  g_scale[COUT];
__device__ float  g_bias[COUT];
__device__ int    g_is64;

#define MMA_BF16(D, A, B)                                                     \
    asm volatile("mma.sync.aligned.m16n8k16.row.col.f32.bf16.bf16.f32 "       \
                 "{%0,%1,%2,%3}, {%4,%5,%6,%7}, {%8,%9}, {%0,%1,%2,%3};"      \
                 : "+f"((D)[0]), "+f"((D)[1]), "+f"((D)[2]), "+f"((D)[3])     \
                 : "r"((A)[0]), "r"((A)[1]), "r"((A)[2]), "r"((A)[3]),        \
                   "r"((B).x), "r"((B).y))

// ---------------------------------------------------------------------------
// Kernel 0: detect int64 vs int32 neigh (JAX x64 off => i32). Sample odd words.
// ---------------------------------------------------------------------------
__global__ void detect_kernel(const unsigned int* __restrict__ nv) {
    __shared__ int ok;
    if (threadIdx.x == 0) ok = 1;
    __syncthreads();
    unsigned int v = nv[threadIdx.x * 2000 + 1];
    if (v != 0u && v != 0xFFFFFFFFu) ok = 0;
    __syncthreads();
    if (threadIdx.x == 0) g_is64 = ok;
}

// ---------------------------------------------------------------------------
// Kernel 1: build mma B fragments from weights, bf16 hi/lo split.
// B_k[i][o] = w[o][i][k]. Fragment (PTX m16n8k16 B, col): lane l holds
// b0 = {B[2(l%4)][n], B[2(l%4)+1][n]}, b1 = {B[2(l%4)+8][n], B[+9][n]}, n=l/4.
// ---------------------------------------------------------------------------
__global__ void wfrag_kernel(const float* __restrict__ w) {
    int t = blockIdx.x * blockDim.x + threadIdx.x;   // 27*4*32 = 3456
    if (t >= KK * 4 * 32) return;
    int lane = t & 31;
    int nt   = (t >> 5) & 3;
    int k    = t >> 7;
    int o    = nt * 8 + (lane >> 2);
    int i0   = 2 * (lane & 3);
    int ii[4] = {i0, i0 + 1, i0 + 8, i0 + 9};
    unsigned short hi[4], lo[4];
#pragma unroll
    for (int j = 0; j < 4; j++) {
        float vv = w[(o * CIN + ii[j]) * KK + k];
        __nv_bfloat16 bh = __float2bfloat16(vv);
        __nv_bfloat16 bl = __float2bfloat16(vv - __bfloat162float(bh));
        hi[j] = __bfloat16_as_ushort(bh);
        lo[j] = __bfloat16_as_ushort(bl);
    }
    uint2 Hf, Lf;
    Hf.x = (unsigned)hi[0] | ((unsigned)hi[1] << 16);
    Hf.y = (unsigned)hi[2] | ((unsigned)hi[3] << 16);
    Lf.x = (unsigned)lo[0] | ((unsigned)lo[1] << 16);
    Lf.y = (unsigned)lo[2] | ((unsigned)lo[3] << 16);
    g_bfrag[((k * 2 + 0) * 4 + nt) * 32 + lane] = Hf;
    g_bfrag[((k * 2 + 1) * 4 + nt) * 32 + lane] = Lf;
}

// ---------------------------------------------------------------------------
// Kernel 2: transpose + bf16-split x: g_xbf[h] = 64B row [hi[16] | lo[16]].
// ---------------------------------------------------------------------------
__global__ void split_x_kernel(const float* __restrict__ x) {
    int h = blockIdx.x * blockDim.x + threadIdx.x;
    if (h < H_) {
        unsigned int hw[8], lw[8];
#pragma unroll
        for (int t = 0; t < 8; t++) {
            float v0 = x[(size_t)(2 * t) * H_ + h];
            float v1 = x[(size_t)(2 * t + 1) * H_ + h];
            __nv_bfloat16 h0 = __float2bfloat16(v0), h1 = __float2bfloat16(v1);
            __nv_bfloat16 l0 = __float2bfloat16(v0 - __bfloat162float(h0));
            __nv_bfloat16 l1 = __float2bfloat16(v1 - __bfloat162float(h1));
            hw[t] = (unsigned)__bfloat16_as_ushort(h0) |
                    ((unsigned)__bfloat16_as_ushort(h1) << 16);
            lw[t] = (unsigned)__bfloat16_as_ushort(l0) |
                    ((unsigned)__bfloat16_as_ushort(l1) << 16);
        }
        g_xbf[(size_t)h * 4 + 0] = make_uint4(hw[0], hw[1], hw[2], hw[3]);
        g_xbf[(size_t)h * 4 + 1] = make_uint4(hw[4], hw[5], hw[6], hw[7]);
        g_xbf[(size_t)h * 4 + 2] = make_uint4(lw[0], lw[1], lw[2], lw[3]);
        g_xbf[(size_t)h * 4 + 3] = make_uint4(lw[4], lw[5], lw[6], lw[7]);
    }
}

// ---------------------------------------------------------------------------
// Kernel 3: HMMA conv, warp-local cp.async pipeline: 3 smem stages but
// prefetch distance 3 (issue k+2 BEFORE waiting for k) -> 12 outstanding
// gathers/warp at 6 CTAs/SM. Warp w gathers AND consumes rows 32w..32w+31.
// 27 k16-chunks x 3 split GEMMs (Ah·Bh + Ah·Bl + Al·Bh).
// ---------------------------------------------------------------------------
__global__ void __launch_bounds__(TB, 6) conv_kernel(const int* __restrict__ neigh32,
                                                     float* __restrict__ out) {
    __shared__ __align__(128) char Ab[NSTAGE * STAGEB];   // 30720 B

    const int tid  = threadIdx.x;
    const int lane = tid & 31;
    const int wid  = tid >> 5;
    const int h0   = blockIdx.x * HB;
    const int is64 = g_is64;
    const uint32_t sbase = (uint32_t)__cvta_generic_to_shared(Ab);

    // Warp-local gather mapping: lane -> q = 16B quadrant, rl + 8j = row in warp.
    const int q  = lane & 3;
    const int rl = lane >> 2;       // 0..7

    // issue gather of k-chunk into stage k%3 (4 cp.async per thread, own warp's rows)
    auto issue = [&](int k) {
        uint32_t dstb = sbase + (k % NSTAGE) * STAGEB;
#pragma unroll
        for (int j = 0; j < 4; j++) {
            int r = wid * 32 + rl + 8 * j;    // block-row, within this warp's 32
            int h = h0 + r;
            int idx = -1;
            if (h < H_) {
                int gi = h * KK + k;
                idx = neigh32[is64 ? 2 * gi : gi];
            }
            unsigned ok = ((unsigned)idx < (unsigned)H_) ? 16u : 0u;
            const uint4* src = g_xbf + ((size_t)(ok ? idx : 0) * 4 + q);
            uint32_t dst = dstb + r * ROWB + q * 16;
            asm volatile("cp.async.cg.shared.global [%0], [%1], 16, %2;"
                         :: "r"(dst), "l"(src), "r"(ok) : "memory");
        }
        asm volatile("cp.async.commit_group;" ::: "memory");
    };

    // ldmatrix lane addressing (x4: lane -> matrix l/8, row l%8)
    const int rowl = (lane & 7) + ((lane >> 3) & 1) * 8;   // 0-7,8-15,0-7,8-15
    const int byof = (lane >> 4) * 16;                     // i-halves

    float d[2][4][4];
#pragma unroll
    for (int a = 0; a < 2; a++)
#pragma unroll
        for (int b = 0; b < 4; b++)
#pragma unroll
            for (int c = 0; c < 4; c++) d[a][b][c] = 0.f;

    issue(0); issue(1);

#pragma unroll 1
    for (int k = 0; k < KK; k++) {
        // Prefetch first: buffer (k+2)%3 = (k-1)%3 was consumed last iteration
        // (program order, warp-private rows), so the write is hazard-free.
        if (k + 2 < KK) issue(k + 2);
        else asm volatile("cp.async.commit_group;" ::: "memory");
        asm volatile("cp.async.wait_group 2;" ::: "memory");   // chunk k done
        __syncwarp();

        const uint32_t bufb = sbase + (k % NSTAGE) * STAGEB;
        uint32_t aH[2][4], aL[2][4];
#pragma unroll
        for (int mt = 0; mt < 2; mt++) {
            uint32_t ah = bufb + (wid * 32 + mt * 16 + rowl) * ROWB + byof;
            uint32_t al = ah + 32;
            asm volatile("ldmatrix.sync.aligned.m8n8.x4.shared.b16 {%0,%1,%2,%3}, [%4];"
                         : "=r"(aH[mt][0]), "=r"(aH[mt][1]), "=r"(aH[mt][2]), "=r"(aH[mt][3])
                         : "r"(ah));
            asm volatile("ldmatrix.sync.aligned.m8n8.x4.shared.b16 {%0,%1,%2,%3}, [%4];"
                         : "=r"(aL[mt][0]), "=r"(aL[mt][1]), "=r"(aL[mt][2]), "=r"(aL[mt][3])
                         : "r"(al));
        }
#pragma unroll
        for (int nt = 0; nt < 4; nt++) {
            uint2 bh = g_bfrag[((k * 2 + 0) * 4 + nt) * 32 + lane];
            uint2 bl = g_bfrag[((k * 2 + 1) * 4 + nt) * 32 + lane];
#pragma unroll
            for (int mt = 0; mt < 2; mt++) {
                MMA_BF16(d[mt][nt], aH[mt], bh);   // Ah*Bh
                MMA_BF16(d[mt][nt], aH[mt], bl);   // Ah*Bl
                MMA_BF16(d[mt][nt], aL[mt], bh);   // Al*Bh
            }
        }
        __syncwarp();   // all lanes done reading stage k before it is re-issued
    }
    asm volatile("cp.async.wait_group 0;" ::: "memory");

    // Epilogue: D frag lane l: c0,c1 -> row l/4, cols 2(l%4)+{0,1}; c2,c3 -> row+8.
    const int pidx = blockIdx.x * 4 + wid;
#pragma unroll
    for (int nt = 0; nt < 4; nt++) {
        float s0 = 0.f, s1 = 0.f, q0 = 0.f, q1 = 0.f;
#pragma unroll
        for (int mt = 0; mt < 2; mt++) {
            int h  = h0 + wid * 32 + mt * 16 + (lane >> 2);
            int o0 = nt * 8 + 2 * (lane & 3);
            float c0 = d[mt][nt][0], c1 = d[mt][nt][1];
            float c2 = d[mt][nt][2], c3 = d[mt][nt][3];
            if (h < H_) {
                out[(size_t)o0 * H_ + h]       = c0;
                out[(size_t)(o0 + 1) * H_ + h] = c1;
            }
            if (h + 8 < H_) {
                out[(size_t)o0 * H_ + h + 8]       = c2;
                out[(size_t)(o0 + 1) * H_ + h + 8] = c3;
            }
            s0 += c0 + c2; s1 += c1 + c3;
            q0 += c0 * c0 + c2 * c2; q1 += c1 * c1 + c3 * c3;
        }
#pragma unroll
        for (int off = 4; off < 32; off <<= 1) {
            s0 += __shfl_xor_sync(0xffffffffu, s0, off);
            s1 += __shfl_xor_sync(0xffffffffu, s1, off);
            q0 += __shfl_xor_sync(0xffffffffu, q0, off);
            q1 += __shfl_xor_sync(0xffffffffu, q1, off);
        }
        if ((lane >> 2) == 0) {      // lanes 0..3 hold the 8 o's of this nt
            int o0 = nt * 8 + 2 * lane;
            g_partials[o0 * NPART + pidx]            = s0;
            g_partials[(o0 + 1) * NPART + pidx]      = s1;
            g_partials[(32 + o0) * NPART + pidx]     = q0;
            g_partials[(32 + o0 + 1) * NPART + pidx] = q1;
        }
    }
}

// ---------------------------------------------------------------------------
// Kernel 4a: stats stage 1 — 64 rows x SCHUNK chunks; deterministic fp64 tree.
// ---------------------------------------------------------------------------
__global__ void stats1_kernel() {
    const int row   = blockIdx.x;        // 0..63
    const int chunk = blockIdx.y;        // 0..SCHUNK-1
    const int per   = (NPART + SCHUNK - 1) / SCHUNK;   // 1172
    const int b0    = chunk * per;
    const int b1    = (b0 + per < NPART) ? b0 + per : NPART;
    double s = 0.0;
    for (int b = b0 + threadIdx.x; b < b1; b += blockDim.x)
        s += (double)g_partials[row * NPART + b];
    __shared__ double r[256];
    r[threadIdx.x] = s;
    __syncthreads();
    for (int sft = 128; sft > 0; sft >>= 1) {
        if (threadIdx.x < sft) r[threadIdx.x] += r[threadIdx.x + sft];
        __syncthreads();
    }
    if (threadIdx.x == 0) g_red[row * SCHUNK + chunk] = r[0];
}

// ---------------------------------------------------------------------------
// Kernel 4b: stats stage 2 — fold SCHUNK chunk-sums per channel -> scale/bias.
// ---------------------------------------------------------------------------
__global__ void stats2_kernel(const float* __restrict__ gamma,
                              const float* __restrict__ beta) {
    const int o = blockIdx.x;
    if (threadIdx.x == 0) {
        double s1 = 0.0, s2 = 0.0;
#pragma unroll
        for (int c = 0; c < SCHUNK; c++) {
            s1 += g_red[o * SCHUNK + c];
            s2 += g_red[(32 + o) * SCHUNK + c];
        }
        double mean = s1 / (double)H_;
        double var  = s2 / (double)H_ - mean * mean;
        float rstd  = rsqrtf((float)(var + 1e-5));
        float sc    = rstd * gamma[o];
        g_scale[o]  = sc;
        g_bias[o]   = beta[o] - (float)mean * sc;
    }
}

// ---------------------------------------------------------------------------
// Kernel 5: normalize in place (float4; H % 4 == 0).
// ---------------------------------------------------------------------------
__global__ void bn_kernel(float* __restrict__ out) {
    const int o = blockIdx.y;
    const int t = blockIdx.x * blockDim.x + threadIdx.x;
    const float sc = g_scale[o], bi = g_bias[o];
    float4* p = reinterpret_cast<float4*>(out + (size_t)o * H_);
    if (t < H_ / 4) {
        float4 v = p[t];
        v.x = v.x * sc + bi;
        v.y = v.y * sc + bi;
        v.z = v.z * sc + bi;
        v.w = v.w * sc + bi;
        p[t] = v;
    }
}

// ---------------------------------------------------------------------------
extern "C" void kernel_launch(void* const* d_in, const int* in_sizes, int n_in,
                              void* d_out, int out_size) {
    const float* x     = (const float*)d_in[0];  // (1,16,300000,1)
    const float* w     = (const float*)d_in[1];  // (32,16,27)
    const float* gamma = (const float*)d_in[2];  // (32,)
    const float* beta  = (const float*)d_in[3];  // (32,)
    const void*  neigh = d_in[4];                // (300000,27) i64 or i32
    float*       out   = (float*)d_out;          // (1,32,300000,1)

    cudaFuncSetAttribute(conv_kernel,
                         cudaFuncAttributePreferredSharedMemoryCarveout,
                         cudaSharedmemCarveoutMaxShared);

    detect_kernel<<<1, 1024>>>((const unsigned int*)neigh);
    wfrag_kernel<<<(KK * 4 * 32 + 255) / 256, 256>>>(w);
    split_x_kernel<<<(H_ + 255) / 256, 256>>>(x);
    conv_kernel<<<NBLK, TB>>>((const int*)neigh, out);
    stats1_kernel<<<dim3(64, SCHUNK), 256>>>();
    stats2_kernel<<<COUT, 32>>>(gamma, beta);
    bn_kernel<<<dim3((H_ / 4 + 255) / 256, COUT), 256>>>(out);
}

// round 14
// speedup vs baseline: 2.5346x; 1.0175x over previous
#include <cuda_runtime.h>
#include <cuda_bf16.h>
#include <cstdint>
#include <cstddef>

#define H_    300000
#define CIN   16
#define COUT  32
#define KK    27
#define HB    128
#define TB    128
#define NBLK  ((H_ + HB - 1) / HB)    // 2344
#define NPART (NBLK * 4)              // one partial per (o, block, warp)
#define NIDX  (H_ * KK)
#define ROWB  80                      // A row stride: hi(32B) | lo(32B) | pad(16B)
#define STAGEB (HB * ROWB)            // 10240 B per stage
#define NSTAGE 3
#define SCHUNK 8                      // stats reduction chunks per row
#define PREPB  ((H_ + 255) / 256)     // 1172 split_x blocks in merged prep

// Scratch (static device globals: allocation-free per harness rules)
__device__ uint4  g_xbf[(size_t)H_ * 4];       // per h: 64B = 16 hi bf16 | 16 lo bf16
__device__ uint2  g_bfrag[KK * 2 * 4 * 32];    // mma B fragments [(k*2+s)*4+nt][lane]
__device__ float  g_partials[64 * NPART];
__device__ double g_red[64 * SCHUNK];          // stats stage-1 output
__device__ float  g_scale[COUT];
__device__ float  g_bias[COUT];
__device__ int    g_is64;

#define MMA_BF16(D, A, B)                                                     \
    asm volatile("mma.sync.aligned.m16n8k16.row.col.f32.bf16.bf16.f32 "       \
                 "{%0,%1,%2,%3}, {%4,%5,%6,%7}, {%8,%9}, {%0,%1,%2,%3};"      \
                 : "+f"((D)[0]), "+f"((D)[1]), "+f"((D)[2]), "+f"((D)[3])     \
                 : "r"((A)[0]), "r"((A)[1]), "r"((A)[2]), "r"((A)[3]),        \
                   "r"((B).x), "r"((B).y))

// ---------------------------------------------------------------------------
// Kernel 1 (merged prep): blocks [0, PREPB) = split_x; PREPB..PREPB+13 = wfrag;
// last block = detect. All three are independent; conv runs in a later launch.
// ---------------------------------------------------------------------------
__global__ void prep_kernel(const float* __restrict__ x,
                            const float* __restrict__ w,
                            const unsigned int* __restrict__ nv) {
    const int b = blockIdx.x;
    if (b < PREPB) {
        // --- split_x: transpose + bf16 hi/lo split, 64B row per h ---
        int h = b * 256 + threadIdx.x;
        if (h < H_) {
            unsigned int hw[8], lw[8];
#pragma unroll
            for (int t = 0; t < 8; t++) {
                float v0 = x[(size_t)(2 * t) * H_ + h];
                float v1 = x[(size_t)(2 * t + 1) * H_ + h];
                __nv_bfloat16 h0 = __float2bfloat16(v0), h1 = __float2bfloat16(v1);
                __nv_bfloat16 l0 = __float2bfloat16(v0 - __bfloat162float(h0));
                __nv_bfloat16 l1 = __float2bfloat16(v1 - __bfloat162float(h1));
                hw[t] = (unsigned)__bfloat16_as_ushort(h0) |
                        ((unsigned)__bfloat16_as_ushort(h1) << 16);
                lw[t] = (unsigned)__bfloat16_as_ushort(l0) |
                        ((unsigned)__bfloat16_as_ushort(l1) << 16);
            }
            g_xbf[(size_t)h * 4 + 0] = make_uint4(hw[0], hw[1], hw[2], hw[3]);
            g_xbf[(size_t)h * 4 + 1] = make_uint4(hw[4], hw[5], hw[6], hw[7]);
            g_xbf[(size_t)h * 4 + 2] = make_uint4(lw[0], lw[1], lw[2], lw[3]);
            g_xbf[(size_t)h * 4 + 3] = make_uint4(lw[4], lw[5], lw[6], lw[7]);
        }
    } else if (b < PREPB + 14) {
        // --- wfrag: mma B fragments (m16n8k16 col layout), bf16 hi/lo ---
        int t = (b - PREPB) * 256 + threadIdx.x;   // 0..3583, need 3456
        if (t < KK * 4 * 32) {
            int lane = t & 31;
            int nt   = (t >> 5) & 3;
            int k    = t >> 7;
            int o    = nt * 8 + (lane >> 2);
            int i0   = 2 * (lane & 3);
            int ii[4] = {i0, i0 + 1, i0 + 8, i0 + 9};
            unsigned short hi[4], lo[4];
#pragma unroll
            for (int j = 0; j < 4; j++) {
                float vv = w[(o * CIN + ii[j]) * KK + k];
                __nv_bfloat16 bh = __float2bfloat16(vv);
                __nv_bfloat16 bl = __float2bfloat16(vv - __bfloat162float(bh));
                hi[j] = __bfloat16_as_ushort(bh);
                lo[j] = __bfloat16_as_ushort(bl);
            }
            uint2 Hf, Lf;
            Hf.x = (unsigned)hi[0] | ((unsigned)hi[1] << 16);
            Hf.y = (unsigned)hi[2] | ((unsigned)hi[3] << 16);
            Lf.x = (unsigned)lo[0] | ((unsigned)lo[1] << 16);
            Lf.y = (unsigned)lo[2] | ((unsigned)lo[3] << 16);
            g_bfrag[((k * 2 + 0) * 4 + nt) * 32 + lane] = Hf;
            g_bfrag[((k * 2 + 1) * 4 + nt) * 32 + lane] = Lf;
        }
    } else {
        // --- detect int64 vs int32 neigh: sample odd 32-bit words ---
        __shared__ int ok;
        if (threadIdx.x == 0) ok = 1;
        __syncthreads();
        unsigned int v = nv[threadIdx.x * 8000 + 1];   // 256 samples, idx < 2.05M
        if (v != 0u && v != 0xFFFFFFFFu) ok = 0;       // benign race: only writes 0
        __syncthreads();
        if (threadIdx.x == 0) g_is64 = ok;
    }
}

// ---------------------------------------------------------------------------
// Kernel 2: HMMA conv, warp-local cp.async pipeline (3 stages, depth 3) with
// REGISTER-PREFETCHED indices: the 4 neigh indices for the chunk to be issued
// are loaded one full chunk earlier, so cp.async issue never waits on an LDG.
// Warp w gathers AND consumes rows 32w..32w+31. 27 k16-chunks x 3 split GEMMs.
// ---------------------------------------------------------------------------
__global__ void __launch_bounds__(TB, 6) conv_kernel(const int* __restrict__ neigh32,
                                                     float* __restrict__ out) {
    __shared__ __align__(128) char Ab[NSTAGE * STAGEB];   // 30720 B

    const int tid  = threadIdx.x;
    const int lane = tid & 31;
    const int wid  = tid >> 5;
    const int h0   = blockIdx.x * HB;
    const int is64 = g_is64;
    const uint32_t sbase = (uint32_t)__cvta_generic_to_shared(Ab);

    // Warp-local gather mapping: lane -> q = 16B quadrant, rl + 8j = row in warp.
    const int q  = lane & 3;
    const int rl = lane >> 2;       // 0..7
    const int step = is64 ? 2 : 1;

    // Per-row constants: smem dst offset, pre-scaled neigh base, validity.
    uint32_t dsto[4];
    int      gbase[4];
    bool     rvalid[4];
#pragma unroll
    for (int j = 0; j < 4; j++) {
        int r     = wid * 32 + rl + 8 * j;
        dsto[j]   = (uint32_t)(r * ROWB + q * 16);
        int h     = h0 + r;
        rvalid[j] = (h < H_);
        gbase[j]  = (rvalid[j] ? h : 0) * KK * step;
    }

    // Load the 4 indices for chunk k into pidx (one LDG each, coalesced-ish).
    int pidx[4];
    auto loadidx = [&](int k) {
#pragma unroll
        for (int j = 0; j < 4; j++)
            pidx[j] = rvalid[j] ? neigh32[gbase[j] + k * step] : -1;
    };
    // Issue gathers for chunk k using the already-loaded pidx.
    auto issue = [&](int k) {
        uint32_t dstb = sbase + (k % NSTAGE) * STAGEB;
#pragma unroll
        for (int j = 0; j < 4; j++) {
            unsigned ok = ((unsigned)pidx[j] < (unsigned)H_) ? 16u : 0u;
            const uint4* src = g_xbf + ((size_t)(ok ? pidx[j] : 0) * 4 + q);
            asm volatile("cp.async.cg.shared.global [%0], [%1], 16, %2;"
                         :: "r"(dstb + dsto[j]), "l"(src), "r"(ok) : "memory");
        }
        asm volatile("cp.async.commit_group;" ::: "memory");
    };

    // ldmatrix lane addressing (x4: lane -> matrix l/8, row l%8)
    const int rowl = (lane & 7) + ((lane >> 3) & 1) * 8;
    const int byof = (lane >> 4) * 16;

    float d[2][4][4];
#pragma unroll
    for (int a = 0; a < 2; a++)
#pragma unroll
        for (int b = 0; b < 4; b++)
#pragma unroll
            for (int c = 0; c < 4; c++) d[a][b][c] = 0.f;

    loadidx(0); issue(0);
    loadidx(1); issue(1);
    loadidx(2);

#pragma unroll 1
    for (int k = 0; k < KK; k++) {
        // Issue chunk k+2 from prefetched pidx, then start loading idx k+3.
        // Buffer (k+2)%3 = (k-1)%3 was consumed last iteration (program order,
        // warp-private rows), so the write is hazard-free.
        if (k + 2 < KK) {
            issue(k + 2);
            if (k + 3 < KK) loadidx(k + 3);
        } else {
            asm volatile("cp.async.commit_group;" ::: "memory");
        }
        asm volatile("cp.async.wait_group 2;" ::: "memory");   // chunk k done
        __syncwarp();

        const uint32_t bufb = sbase + (k % NSTAGE) * STAGEB;
        uint32_t aH[2][4], aL[2][4];
#pragma unroll
        for (int mt = 0; mt < 2; mt++) {
            uint32_t ah = bufb + (wid * 32 + mt * 16 + rowl) * ROWB + byof;
            uint32_t al = ah + 32;
            asm volatile("ldmatrix.sync.aligned.m8n8.x4.shared.b16 {%0,%1,%2,%3}, [%4];"
                         : "=r"(aH[mt][0]), "=r"(aH[mt][1]), "=r"(aH[mt][2]), "=r"(aH[mt][3])
                         : "r"(ah));
            asm volatile("ldmatrix.sync.aligned.m8n8.x4.shared.b16 {%0,%1,%2,%3}, [%4];"
                         : "=r"(aL[mt][0]), "=r"(aL[mt][1]), "=r"(aL[mt][2]), "=r"(aL[mt][3])
                         : "r"(al));
        }
#pragma unroll
        for (int nt = 0; nt < 4; nt++) {
            uint2 bh = __ldg(&g_bfrag[((k * 2 + 0) * 4 + nt) * 32 + lane]);
            uint2 bl = __ldg(&g_bfrag[((k * 2 + 1) * 4 + nt) * 32 + lane]);
#pragma unroll
            for (int mt = 0; mt < 2; mt++) {
                MMA_BF16(d[mt][nt], aH[mt], bh);   // Ah*Bh
                MMA_BF16(d[mt][nt], aH[mt], bl);   // Ah*Bl
                MMA_BF16(d[mt][nt], aL[mt], bh);   // Al*Bh
            }
        }
        __syncwarp();   // all lanes done reading stage k before it is re-issued
    }
    asm volatile("cp.async.wait_group 0;" ::: "memory");

    // Epilogue: D frag lane l: c0,c1 -> row l/4, cols 2(l%4)+{0,1}; c2,c3 -> row+8.
    const int pidx2 = blockIdx.x * 4 + wid;
#pragma unroll
    for (int nt = 0; nt < 4; nt++) {
        float s0 = 0.f, s1 = 0.f, q0 = 0.f, q1 = 0.f;
#pragma unroll
        for (int mt = 0; mt < 2; mt++) {
            int h  = h0 + wid * 32 + mt * 16 + (lane >> 2);
            int o0 = nt * 8 + 2 * (lane & 3);
            float c0 = d[mt][nt][0], c1 = d[mt][nt][1];
            float c2 = d[mt][nt][2], c3 = d[mt][nt][3];
            if (h < H_) {
                out[(size_t)o0 * H_ + h]       = c0;
                out[(size_t)(o0 + 1) * H_ + h] = c1;
            }
            if (h + 8 < H_) {
                out[(size_t)o0 * H_ + h + 8]       = c2;
                out[(size_t)(o0 + 1) * H_ + h + 8] = c3;
            }
            s0 += c0 + c2; s1 += c1 + c3;
            q0 += c0 * c0 + c2 * c2; q1 += c1 * c1 + c3 * c3;
        }
#pragma unroll
        for (int off = 4; off < 32; off <<= 1) {
            s0 += __shfl_xor_sync(0xffffffffu, s0, off);
            s1 += __shfl_xor_sync(0xffffffffu, s1, off);
            q0 += __shfl_xor_sync(0xffffffffu, q0, off);
            q1 += __shfl_xor_sync(0xffffffffu, q1, off);
        }
        if ((lane >> 2) == 0) {      // lanes 0..3 hold the 8 o's of this nt
            int o0 = nt * 8 + 2 * lane;
            g_partials[o0 * NPART + pidx2]            = s0;
            g_partials[(o0 + 1) * NPART + pidx2]      = s1;
            g_partials[(32 + o0) * NPART + pidx2]     = q0;
            g_partials[(32 + o0 + 1) * NPART + pidx2] = q1;
        }
    }
}

// ---------------------------------------------------------------------------
// Kernel 3a: stats stage 1 — 64 rows x SCHUNK chunks; deterministic fp64 tree.
// ---------------------------------------------------------------------------
__global__ void stats1_kernel() {
    const int row   = blockIdx.x;        // 0..63
    const int chunk = blockIdx.y;        // 0..SCHUNK-1
    const int per   = (NPART + SCHUNK - 1) / SCHUNK;   // 1172
    const int b0    = chunk * per;
    const int b1    = (b0 + per < NPART) ? b0 + per : NPART;
    double s = 0.0;
    for (int b = b0 + threadIdx.x; b < b1; b += blockDim.x)
        s += (double)g_partials[row * NPART + b];
    __shared__ double r[256];
    r[threadIdx.x] = s;
    __syncthreads();
    for (int sft = 128; sft > 0; sft >>= 1) {
        if (threadIdx.x < sft) r[threadIdx.x] += r[threadIdx.x + sft];
        __syncthreads();
    }
    if (threadIdx.x == 0) g_red[row * SCHUNK + chunk] = r[0];
}

// ---------------------------------------------------------------------------
// Kernel 3b: stats stage 2 — fold SCHUNK chunk-sums per channel -> scale/bias.
// ---------------------------------------------------------------------------
__global__ void stats2_kernel(const float* __restrict__ gamma,
                              const float* __restrict__ beta) {
    const int o = blockIdx.x;
    if (threadIdx.x == 0) {
        double s1 = 0.0, s2 = 0.0;
#pragma unroll
        for (int c = 0; c < SCHUNK; c++) {
            s1 += g_red[o * SCHUNK + c];
            s2 += g_red[(32 + o) * SCHUNK + c];
        }
        double mean = s1 / (double)H_;
        double var  = s2 / (double)H_ - mean * mean;
        float rstd  = rsqrtf((float)(var + 1e-5));
        float sc    = rstd * gamma[o];
        g_scale[o]  = sc;
        g_bias[o]   = beta[o] - (float)mean * sc;
    }
}

// ---------------------------------------------------------------------------
// Kernel 4: normalize in place (float4; H % 4 == 0).
// ---------------------------------------------------------------------------
__global__ void bn_kernel(float* __restrict__ out) {
    const int o = blockIdx.y;
    const int t = blockIdx.x * blockDim.x + threadIdx.x;
    const float sc = g_scale[o], bi = g_bias[o];
    float4* p = reinterpret_cast<float4*>(out + (size_t)o * H_);
    if (t < H_ / 4) {
        float4 v = p[t];
        v.x = v.x * sc + bi;
        v.y = v.y * sc + bi;
        v.z = v.z * sc + bi;
        v.w = v.w * sc + bi;
        p[t] = v;
    }
}

// ---------------------------------------------------------------------------
extern "C" void kernel_launch(void* const* d_in, const int* in_sizes, int n_in,
                              void* d_out, int out_size) {
    const float* x     = (const float*)d_in[0];  // (1,16,300000,1)
    const float* w     = (const float*)d_in[1];  // (32,16,27)
    const float* gamma = (const float*)d_in[2];  // (32,)
    const float* beta  = (const float*)d_in[3];  // (32,)
    const void*  neigh = d_in[4];                // (300000,27) i64 or i32
    float*       out   = (float*)d_out;          // (1,32,300000,1)

    cudaFuncSetAttribute(conv_kernel,
                         cudaFuncAttributePreferredSharedMemoryCarveout,
                         cudaSharedmemCarveoutMaxShared);

    prep_kernel<<<PREPB + 15, 256>>>(x, w, (const unsigned int*)neigh);
    conv_kernel<<<NBLK, TB>>>((const int*)neigh, out);
    stats1_kernel<<<dim3(64, SCHUNK), 256>>>();
    stats2_kernel<<<COUT, 32>>>(gamma, beta);
    bn_kernel<<<dim3((H_ / 4 + 255) / 256, COUT), 256>>>(out);
}